// round 13
// baseline (speedup 1.0000x reference)
#include <cuda_runtime.h>
#include <cuda_fp16.h>
#include <math.h>
#include <stdint.h>

// ---------------- problem constants -------------------------------------------
#define BTOK   4096
#define DIN    1024
#define DHID   4096
#define DOUT   1024
#define NE     8
#define TOPK   2
#define MAXROWS (BTOK * TOPK)          // 8192 grouped rows, always exact
#define BM     128
#define BN     128
#define BK     32
#define MAXTILES (MAXROWS / BM + NE)   // 72 worst-case m-tiles

#define GT     128                     // GEMM threads per CTA (4 warps)

#define RT_THREADS 256
#define TOK_PER_TH (BTOK / RT_THREADS) // 16

// ---------------- smem tile geometry --------------------------------------------
#define A_STRIDE 80                     // bytes per A row: 32 fp16 (64B) + 16B pad
#define B_STRIDE 272                    // bytes per B k-row: 128 fp16 (256B) + 16B pad
#define A_REG (BM * A_STRIDE)           // 10240
#define B_REG (BK * B_STRIDE)           // 8704
#define STG_BYTES (A_REG + B_REG)       // 18944 per stage
#define NSTAGE 3
#define SMEM_TOTAL (NSTAGE * STG_BYTES) // 56832 (3 CTAs/SM -> 170 KB)

// quad counts for the fused fp32->fp16 conversion (4 floats -> 2 words each)
#define XQUADS (BTOK * (size_t)DIN / 4)
#define WQUADS ((size_t)NE * DIN * DHID / 4)
#define ALLQUADS (XQUADS + 2 * WQUADS)       // 17,825,792

// ---------------- device scratch (device-code-only access!) --------------------
__device__ uint32_t g_xh[BTOK * (size_t)(DIN / 2)];          // fp16x2
__device__ uint32_t g_w1h[(size_t)NE * DIN * DHID / 2];
__device__ uint32_t g_w2h[(size_t)NE * DHID * DOUT / 2];
__device__ uint32_t g_hh[MAXROWS * (size_t)(DHID / 2)];
__device__ float    g_y[MAXROWS * (size_t)DOUT];
__device__ float    g_gates[BTOK * NE];
__device__ float    g_topw[BTOK * TOPK];
__device__ int      g_topi[BTOK * TOPK];
__device__ int      g_counts[NE];
__device__ int      g_token_of_row[MAXROWS];
__device__ int      g_row_of[BTOK * TOPK];

// ---------------- helpers -------------------------------------------------------
__device__ __forceinline__ uint32_t smem_u32(const void* p) {
    uint32_t a;
    asm("{ .reg .u64 t; cvta.to.shared.u64 t, %1; cvt.u32.u64 %0, t; }"
        : "=r"(a) : "l"(p));
    return a;
}

__device__ __forceinline__ void ldsm4(uint32_t* r, uint32_t addr) {
    asm volatile("ldmatrix.sync.aligned.m8n8.x4.shared.b16 {%0,%1,%2,%3}, [%4];"
                 : "=r"(r[0]), "=r"(r[1]), "=r"(r[2]), "=r"(r[3]) : "r"(addr));
}

__device__ __forceinline__ void ldsm4t(uint32_t* r, uint32_t addr) {
    asm volatile("ldmatrix.sync.aligned.m8n8.x4.trans.shared.b16 {%0,%1,%2,%3}, [%4];"
                 : "=r"(r[0]), "=r"(r[1]), "=r"(r[2]), "=r"(r[3]) : "r"(addr));
}

__device__ __forceinline__ void mma_f16(float* c, const uint32_t* a,
                                        uint32_t b0, uint32_t b1) {
    asm volatile(
        "mma.sync.aligned.m16n8k16.row.col.f32.f16.f16.f32 "
        "{%0,%1,%2,%3}, {%4,%5,%6,%7}, {%8,%9}, {%0,%1,%2,%3};"
        : "+f"(c[0]), "+f"(c[1]), "+f"(c[2]), "+f"(c[3])
        : "r"(a[0]), "r"(a[1]), "r"(a[2]), "r"(a[3]), "r"(b0), "r"(b1));
}

__device__ __forceinline__ void cp16(uint32_t dst, const void* src) {
    asm volatile("cp.async.cg.shared.global [%0], [%1], 16;"
                 :: "r"(dst), "l"(src));
}
#define CP_COMMIT() asm volatile("cp.async.commit_group;" ::: "memory")
#define CP_WAIT1()  asm volatile("cp.async.wait_group 1;" ::: "memory")
#define CP_WAIT0()  asm volatile("cp.async.wait_group 0;" ::: "memory")

__device__ __forceinline__ uint32_t h2u(__half2 h) {
    return *reinterpret_cast<uint32_t*>(&h);
}

// ---------------- fused convert: x, W1, W2 -> fp16 ------------------------------
__global__ void convert_all_kernel(const float* __restrict__ x,
                                   const float* __restrict__ W1,
                                   const float* __restrict__ W2) {
    size_t p = (size_t)blockIdx.x * blockDim.x + threadIdx.x;
    if (p >= ALLQUADS) return;
    const float* src;
    uint32_t* dst;
    size_t q;
    if (p < XQUADS)               { q = p;                    src = x;  dst = g_xh;  }
    else if (p < XQUADS + WQUADS) { q = p - XQUADS;           src = W1; dst = g_w1h; }
    else                          { q = p - XQUADS - WQUADS;  src = W2; dst = g_w2h; }
    float4 v = ((const float4*)src)[q];
    dst[q * 2 + 0] = h2u(__floats2half2_rn(v.x, v.y));
    dst[q * 2 + 1] = h2u(__floats2half2_rn(v.z, v.w));
}

// ---------------- gating / routing / loss --------------------------------------

__global__ void gating_kernel(const float* __restrict__ x,
                              const float* __restrict__ Wg,
                              const float* __restrict__ bg) {
    int gwarp = (blockIdx.x * blockDim.x + threadIdx.x) >> 5;
    int lane  = threadIdx.x & 31;
    if (gwarp >= BTOK) return;
    const float* xr = x + (size_t)gwarp * DIN;

    float acc[NE];
#pragma unroll
    for (int e = 0; e < NE; e++) acc[e] = 0.f;

    for (int i = lane; i < DIN; i += 32) {
        float xv = xr[i];
        const float4* wg4 = (const float4*)(Wg + (size_t)i * NE);
        float4 w0 = wg4[0];
        float4 w1 = wg4[1];
        acc[0] += xv * w0.x; acc[1] += xv * w0.y;
        acc[2] += xv * w0.z; acc[3] += xv * w0.w;
        acc[4] += xv * w1.x; acc[5] += xv * w1.y;
        acc[6] += xv * w1.z; acc[7] += xv * w1.w;
    }
#pragma unroll
    for (int e = 0; e < NE; e++)
#pragma unroll
        for (int o = 16; o > 0; o >>= 1)
            acc[e] += __shfl_xor_sync(0xffffffffu, acc[e], o);

    if (lane == 0) {
        float logit[NE];
#pragma unroll
        for (int e = 0; e < NE; e++) logit[e] = acc[e] + bg[e];

        float mx = logit[0];
#pragma unroll
        for (int e = 1; e < NE; e++) mx = fmaxf(mx, logit[e]);
        float s = 0.f, ex[NE];
#pragma unroll
        for (int e = 0; e < NE; e++) { ex[e] = expf(logit[e] - mx); s += ex[e]; }
        float inv = 1.f / s;
#pragma unroll
        for (int e = 0; e < NE; e++) g_gates[gwarp * NE + e] = ex[e] * inv;

        int i0 = 0;
#pragma unroll
        for (int e = 1; e < NE; e++) if (logit[e] > logit[i0]) i0 = e;
        int i1 = -1;
#pragma unroll
        for (int e = 0; e < NE; e++)
            if (e != i0 && (i1 < 0 || logit[e] > logit[i1])) i1 = e;

        float w0 = 1.f / (1.f + expf(logit[i1] - logit[i0]));
        g_topi[gwarp * 2 + 0] = i0;
        g_topi[gwarp * 2 + 1] = i1;
        g_topw[gwarp * 2 + 0] = w0;
        g_topw[gwarp * 2 + 1] = 1.f - w0;
    }
}

__global__ void route_kernel() {
    __shared__ int hist[RT_THREADS][NE];
    __shared__ int offs_sh[NE];
    __shared__ int counts_sh[NE];
    int tid = threadIdx.x;

    int h[NE];
#pragma unroll
    for (int e = 0; e < NE; e++) h[e] = 0;
    int t0 = tid * TOK_PER_TH;
    for (int i = 0; i < TOK_PER_TH; i++) {
        int t = t0 + i;
        h[g_topi[t * 2 + 0]]++;
        h[g_topi[t * 2 + 1]]++;
    }
#pragma unroll
    for (int e = 0; e < NE; e++) hist[tid][e] = h[e];
    __syncthreads();

    if (tid < NE) {
        int e = tid, s = 0;
        for (int j = 0; j < RT_THREADS; j++) {
            int v = hist[j][e];
            hist[j][e] = s;
            s += v;
        }
        counts_sh[e] = s;
        g_counts[e]  = s;
    }
    __syncthreads();

    if (tid == 0) {
        int off = 0;
        for (int e = 0; e < NE; e++) { offs_sh[e] = off; off += counts_sh[e]; }
    }
    __syncthreads();

    int base[NE];
#pragma unroll
    for (int e = 0; e < NE; e++) base[e] = offs_sh[e] + hist[tid][e];

    for (int i = 0; i < TOK_PER_TH; i++) {
        int t = t0 + i;
#pragma unroll
        for (int k = 0; k < TOPK; k++) {
            int e   = g_topi[t * 2 + k];
            int row = base[e]++;
            g_token_of_row[row] = t;
            g_row_of[t * 2 + k] = row;
        }
    }
}

// Fused per-expert usage mean + load-balance loss (single block, deterministic).
__global__ void usage_loss_kernel(float* __restrict__ out, int out_size) {
    __shared__ float s[256][NE];
    int tid = threadIdx.x;
    float acc[NE];
#pragma unroll
    for (int e = 0; e < NE; e++) acc[e] = 0.f;
    for (int t = tid; t < BTOK; t += 256) {
        const float* g = g_gates + (size_t)t * NE;
#pragma unroll
        for (int e = 0; e < NE; e++) acc[e] += g[e];
    }
#pragma unroll
    for (int e = 0; e < NE; e++) s[tid][e] = acc[e];
    __syncthreads();
    if (tid == 0) {
        float loss = 0.f;
        for (int e = 0; e < NE; e++) {
            float u = 0.f;
            for (int j = 0; j < 256; j++) u += s[j][e];
            u /= (float)BTOK;
            loss += u * u;
        }
        if (out_size > BTOK * DOUT) out[BTOK * DOUT] = (float)NE * loss;
    }
}

// ---------------- grouped GEMM: cp.async (3-stage) + fp16 HMMA, 64x64 warp tile --
// 128 threads (4 warps, 2m x 2n), warp tile 64x64 -> 4 mma per ldsm.x4.
// __launch_bounds__(128, 3): 3 CTAs/SM, 12 warps, 3 independent barrier domains.
// STAGE=1: A = g_xh (gathered rows) -> g_hh (fp16x2), ReLU.
// STAGE=2: A = g_hh (contiguous)    -> g_y (fp32).
template <int KD, int ND, int STAGE>
__global__ void __launch_bounds__(GT, 3)
moe_gemm_f16(const float* __restrict__ bias) {
    int t = blockIdx.x;

    int e = 0, grow0 = 0, rows = 0;
    {
        int tileacc = 0, off = 0;
        bool found = false;
#pragma unroll
        for (int ee = 0; ee < NE; ee++) {
            int c  = g_counts[ee];
            int nt = (c + BM - 1) / BM;
            if (!found && t < tileacc + nt) {
                found = true;
                e     = ee;
                int rb = (t - tileacc) * BM;
                grow0 = off + rb;
                rows  = min(BM, c - rb);
            }
            tileacc += nt;
            off     += c;
        }
        if (!found) return;
    }
    int n0 = blockIdx.y * BN;

    extern __shared__ __align__(16) uint8_t dynsmem[];
    uint32_t sbase = smem_u32(dynsmem);

    int tid = threadIdx.x, wid = tid >> 5, lane = tid & 31;
    int warp_m = wid & 1;        // 0..1 -> m offset *64
    int warp_n = wid >> 1;       // 0..1 -> n offset *64

    // ---- cp.async source pointers ----
    // A: thread -> one full row (32 fp16 = 64 B = 4x16B)
    int arow = tid;
    const uint32_t* Asrc;
    if (STAGE == 1) {
        int tok = (arow < rows) ? g_token_of_row[grow0 + arow] : g_token_of_row[grow0];
        Asrc = g_xh + (size_t)tok * (KD / 2);
    } else {
        int r = min(grow0 + arow, MAXROWS - 1);
        Asrc = g_hh + (size_t)r * (KD / 2);
    }
    // B: thread -> (k-row, 64B segment)
    int bkrow = tid >> 2, bseg = tid & 3;
    const uint32_t* Wsrc = (STAGE == 1 ? g_w1h : g_w2h)
                           + ((size_t)e * KD + bkrow) * (ND / 2) + n0 / 2 + bseg * 16;

    // ---- ldmatrix address bases ----
    uint32_t a_off = (uint32_t)(warp_m * 64 + (lane & 15)) * A_STRIDE
                   + (uint32_t)(lane >> 4) * 16;
    uint32_t b_off = (uint32_t)((lane & 7) + ((lane >> 3) & 1) * 8) * B_STRIDE
                   + (uint32_t)(warp_n * 64 + ((lane >> 4) & 1) * 8) * 2;

    float acc[4][8][4];
#pragma unroll
    for (int i = 0; i < 4; i++)
#pragma unroll
        for (int j = 0; j < 8; j++)
#pragma unroll
            for (int q = 0; q < 4; q++) acc[i][j][q] = 0.f;

    const int NCH = KD / BK;

    auto issue = [&](int it) {
        uint32_t base = sbase + (uint32_t)(it % NSTAGE) * STG_BYTES;
        int k0 = it * BK;
        uint32_t dA = base + (uint32_t)arow * A_STRIDE;
        const uint32_t* sa = Asrc + (k0 >> 1);
        cp16(dA,      sa);
        cp16(dA + 16, sa + 4);
        cp16(dA + 32, sa + 8);
        cp16(dA + 48, sa + 12);
        uint32_t dB = base + A_REG + (uint32_t)bkrow * B_STRIDE + (uint32_t)bseg * 64;
        const uint32_t* sb = Wsrc + (size_t)k0 * (ND / 2);
        cp16(dB,      sb);
        cp16(dB + 16, sb + 4);
        cp16(dB + 32, sb + 8);
        cp16(dB + 48, sb + 12);
        CP_COMMIT();
    };

    // prologue: 2 chunks in flight
    issue(0);
    issue(1);

    for (int it = 0; it < NCH; it++) {
        if (it < NCH - 1) CP_WAIT1(); else CP_WAIT0();
        __syncthreads();
        // refill slot (it+2)%3 == (it-1)%3, consumed before the barrier above
        if (it + 2 < NCH) issue(it + 2);

        uint32_t base = sbase + (uint32_t)(it % NSTAGE) * STG_BYTES;
        uint32_t Ab = base, Bb = base + A_REG;

#pragma unroll
        for (int h = 0; h < 2; h++) {
            uint32_t fA[4][4];
#pragma unroll
            for (int mi = 0; mi < 4; mi++)
                ldsm4(fA[mi], Ab + a_off + (uint32_t)mi * (16 * A_STRIDE)
                                         + (uint32_t)h * 32);
#pragma unroll
            for (int n2 = 0; n2 < 4; n2++) {
                uint32_t fB[4];
                ldsm4t(fB, Bb + b_off + (uint32_t)h * (16 * B_STRIDE)
                                      + (uint32_t)n2 * 32);
#pragma unroll
                for (int mi = 0; mi < 4; mi++) {
                    mma_f16(acc[mi][2 * n2],     fA[mi], fB[0], fB[1]);
                    mma_f16(acc[mi][2 * n2 + 1], fA[mi], fB[2], fB[3]);
                }
            }
        }
    }

    // ---- epilogue ----
#pragma unroll
    for (int mi = 0; mi < 4; mi++) {
        int m_lo = warp_m * 64 + mi * 16 + (lane >> 2);
#pragma unroll
        for (int ni = 0; ni < 8; ni++) {
            int ncol = warp_n * 64 + ni * 8 + 2 * (lane & 3);
            float b0 = bias[(size_t)e * ND + n0 + ncol];
            float b1 = bias[(size_t)e * ND + n0 + ncol + 1];
#pragma unroll
            for (int half = 0; half < 2; half++) {
                int m = m_lo + half * 8;
                if (m < rows) {
                    float v0 = acc[mi][ni][2 * half]     + b0;
                    float v1 = acc[mi][ni][2 * half + 1] + b1;
                    size_t grow = (size_t)(grow0 + m);
                    if (STAGE == 1) {
                        v0 = fmaxf(v0, 0.f);
                        v1 = fmaxf(v1, 0.f);
                        g_hh[grow * (ND / 2) + (size_t)(n0 + ncol) / 2] =
                            h2u(__floats2half2_rn(v0, v1));
                    } else {
                        float* cp = g_y + grow * ND + n0 + ncol;
                        cp[0] = v0;
                        cp[1] = v1;
                    }
                }
            }
        }
    }
}

// out[t] = w0 * y[row0] + w1 * y[row1]
__global__ void combine_kernel(float* __restrict__ out) {
    int t = blockIdx.x;
    int r0 = g_row_of[t * 2 + 0];
    int r1 = g_row_of[t * 2 + 1];
    float w0 = g_topw[t * 2 + 0];
    float w1 = g_topw[t * 2 + 1];
    const float4* y0 = (const float4*)(g_y + (size_t)r0 * DOUT);
    const float4* y1 = (const float4*)(g_y + (size_t)r1 * DOUT);
    float4* o = (float4*)(out + (size_t)t * DOUT);
    for (int j = threadIdx.x; j < DOUT / 4; j += blockDim.x) {
        float4 a = y0[j], b = y1[j];
        float4 r;
        r.x = w0 * a.x + w1 * b.x;
        r.y = w0 * a.y + w1 * b.y;
        r.z = w0 * a.z + w1 * b.z;
        r.w = w0 * a.w + w1 * b.w;
        o[j] = r;
    }
}

// ---------------- launch ---------------------------------------------------------

extern "C" void kernel_launch(void* const* d_in, const int* in_sizes, int n_in,
                              void* d_out, int out_size) {
    const float *x = 0, *Wg = 0, *bg = 0, *W1 = 0, *b1 = 0, *W2 = 0, *b2 = 0;
    for (int i = 0; i < n_in; i++) {
        const float* p = (const float*)d_in[i];
        switch (in_sizes[i]) {
            case BTOK * DIN:        x  = p; break;                        // 4194304
            case NE:                bg = p; break;                        // 8
            case NE * DHID:         b1 = p; break;                        // 32768
            case NE * DIN * DHID:   if (!W1) W1 = p; else W2 = p; break;  // 33554432
            case DIN * NE:          if (!Wg) Wg = p; else b2 = p; break;  // 8192
            default: break;
        }
    }
    if (!(x && Wg && bg && W1 && b1 && W2 && b2)) {
        x  = (const float*)d_in[0]; Wg = (const float*)d_in[1];
        bg = (const float*)d_in[2]; W1 = (const float*)d_in[3];
        b1 = (const float*)d_in[4]; W2 = (const float*)d_in[5];
        b2 = (const float*)d_in[6];
    }
    float* out = (float*)d_out;

    cudaFuncSetAttribute(moe_gemm_f16<DIN, DHID, 1>,
                         cudaFuncAttributeMaxDynamicSharedMemorySize, SMEM_TOTAL);
    cudaFuncSetAttribute(moe_gemm_f16<DHID, DOUT, 2>,
                         cudaFuncAttributeMaxDynamicSharedMemorySize, SMEM_TOTAL);

    convert_all_kernel<<<(int)((ALLQUADS + 255) / 256), 256>>>(x, W1, W2); // 1
    gating_kernel<<<BTOK / 8, 256>>>(x, Wg, bg);                           // 2
    route_kernel<<<1, RT_THREADS>>>();                                     // 3

    moe_gemm_f16<DIN, DHID, 1>                                             // 4 (ncu)
        <<<dim3(MAXTILES, DHID / BN), GT, SMEM_TOTAL>>>(b1);

    usage_loss_kernel<<<1, 256>>>(out, out_size);                          // 5

    moe_gemm_f16<DHID, DOUT, 2>                                            // 6
        <<<dim3(MAXTILES, DOUT / BN), GT, SMEM_TOTAL>>>(b2);

    combine_kernel<<<BTOK, 256>>>(out);                                    // 7
}

// round 14
// speedup vs baseline: 1.1081x; 1.1081x over previous
#include <cuda_runtime.h>
#include <cuda_fp16.h>
#include <math.h>
#include <stdint.h>

// ---------------- problem constants -------------------------------------------
#define BTOK   4096
#define DIN    1024
#define DHID   4096
#define DOUT   1024
#define NE     8
#define TOPK   2
#define MAXROWS (BTOK * TOPK)          // 8192 grouped rows, always exact
#define BM     128
#define BN     128
#define BK     64
#define MAXTILES (MAXROWS / BM + NE)   // 72 worst-case m-tiles

#define RT_THREADS 256
#define TOK_PER_TH (BTOK / RT_THREADS) // 16

// ---------------- smem tile geometry --------------------------------------------
#define A_STRIDE 144                    // bytes per A row: 64 fp16 (128B) + 16B pad
#define B_STRIDE 272                    // bytes per B k-row: 128 fp16 (256B) + 16B pad
#define A_REG (BM * A_STRIDE)           // 18432
#define B_REG (BK * B_STRIDE)           // 17408
#define STG_BYTES (A_REG + B_REG)       // 35840 per stage
#define NSTAGE 3
#define SMEM_TOTAL (NSTAGE * STG_BYTES) // 107520 (2 CTAs/SM -> 210 KB)

// quad counts for the fused fp32->fp16 conversion (4 floats -> 2 words each)
#define XQUADS (BTOK * (size_t)DIN / 4)
#define WQUADS ((size_t)NE * DIN * DHID / 4)
#define ALLQUADS (XQUADS + 2 * WQUADS)       // 17,825,792

// ---------------- device scratch (device-code-only access!) --------------------
__device__ uint32_t g_xh[BTOK * (size_t)(DIN / 2)];          // fp16x2
__device__ uint32_t g_w1h[(size_t)NE * DIN * DHID / 2];
__device__ uint32_t g_w2h[(size_t)NE * DHID * DOUT / 2];
__device__ uint32_t g_hh[MAXROWS * (size_t)(DHID / 2)];
__device__ float    g_gates[BTOK * NE];
__device__ float    g_topw[BTOK * TOPK];
__device__ int      g_topi[BTOK * TOPK];
__device__ int      g_counts[NE];
__device__ int      g_token_of_row[MAXROWS];
__device__ float    g_wt_of_row[MAXROWS];

// ---------------- helpers -------------------------------------------------------
__device__ __forceinline__ uint32_t smem_u32(const void* p) {
    uint32_t a;
    asm("{ .reg .u64 t; cvta.to.shared.u64 t, %1; cvt.u32.u64 %0, t; }"
        : "=r"(a) : "l"(p));
    return a;
}

__device__ __forceinline__ void ldsm4(uint32_t* r, uint32_t addr) {
    asm volatile("ldmatrix.sync.aligned.m8n8.x4.shared.b16 {%0,%1,%2,%3}, [%4];"
                 : "=r"(r[0]), "=r"(r[1]), "=r"(r[2]), "=r"(r[3]) : "r"(addr));
}

__device__ __forceinline__ void ldsm4t(uint32_t* r, uint32_t addr) {
    asm volatile("ldmatrix.sync.aligned.m8n8.x4.trans.shared.b16 {%0,%1,%2,%3}, [%4];"
                 : "=r"(r[0]), "=r"(r[1]), "=r"(r[2]), "=r"(r[3]) : "r"(addr));
}

__device__ __forceinline__ void mma_f16(float* c, const uint32_t* a,
                                        uint32_t b0, uint32_t b1) {
    asm volatile(
        "mma.sync.aligned.m16n8k16.row.col.f32.f16.f16.f32 "
        "{%0,%1,%2,%3}, {%4,%5,%6,%7}, {%8,%9}, {%0,%1,%2,%3};"
        : "+f"(c[0]), "+f"(c[1]), "+f"(c[2]), "+f"(c[3])
        : "r"(a[0]), "r"(a[1]), "r"(a[2]), "r"(a[3]), "r"(b0), "r"(b1));
}

__device__ __forceinline__ void cp16(uint32_t dst, const void* src) {
    asm volatile("cp.async.cg.shared.global [%0], [%1], 16;"
                 :: "r"(dst), "l"(src));
}
#define CP_COMMIT() asm volatile("cp.async.commit_group;" ::: "memory")
#define CP_WAIT1()  asm volatile("cp.async.wait_group 1;" ::: "memory")
#define CP_WAIT0()  asm volatile("cp.async.wait_group 0;" ::: "memory")

__device__ __forceinline__ uint32_t h2u(__half2 h) {
    return *reinterpret_cast<uint32_t*>(&h);
}

// ---------------- fused convert: x, W1, W2 -> fp16 ------------------------------
__global__ void convert_all_kernel(const float* __restrict__ x,
                                   const float* __restrict__ W1,
                                   const float* __restrict__ W2) {
    size_t p = (size_t)blockIdx.x * blockDim.x + threadIdx.x;
    if (p >= ALLQUADS) return;
    const float* src;
    uint32_t* dst;
    size_t q;
    if (p < XQUADS)               { q = p;                    src = x;  dst = g_xh;  }
    else if (p < XQUADS + WQUADS) { q = p - XQUADS;           src = W1; dst = g_w1h; }
    else                          { q = p - XQUADS - WQUADS;  src = W2; dst = g_w2h; }
    float4 v = ((const float4*)src)[q];
    dst[q * 2 + 0] = h2u(__floats2half2_rn(v.x, v.y));
    dst[q * 2 + 1] = h2u(__floats2half2_rn(v.z, v.w));
}

// ---------------- gating / routing / loss --------------------------------------

__global__ void gating_kernel(const float* __restrict__ x,
                              const float* __restrict__ Wg,
                              const float* __restrict__ bg) {
    int gwarp = (blockIdx.x * blockDim.x + threadIdx.x) >> 5;
    int lane  = threadIdx.x & 31;
    if (gwarp >= BTOK) return;
    const float* xr = x + (size_t)gwarp * DIN;

    float acc[NE];
#pragma unroll
    for (int e = 0; e < NE; e++) acc[e] = 0.f;

    for (int i = lane; i < DIN; i += 32) {
        float xv = xr[i];
        const float4* wg4 = (const float4*)(Wg + (size_t)i * NE);
        float4 w0 = wg4[0];
        float4 w1 = wg4[1];
        acc[0] += xv * w0.x; acc[1] += xv * w0.y;
        acc[2] += xv * w0.z; acc[3] += xv * w0.w;
        acc[4] += xv * w1.x; acc[5] += xv * w1.y;
        acc[6] += xv * w1.z; acc[7] += xv * w1.w;
    }
#pragma unroll
    for (int e = 0; e < NE; e++)
#pragma unroll
        for (int o = 16; o > 0; o >>= 1)
            acc[e] += __shfl_xor_sync(0xffffffffu, acc[e], o);

    if (lane == 0) {
        float logit[NE];
#pragma unroll
        for (int e = 0; e < NE; e++) logit[e] = acc[e] + bg[e];

        float mx = logit[0];
#pragma unroll
        for (int e = 1; e < NE; e++) mx = fmaxf(mx, logit[e]);
        float s = 0.f, ex[NE];
#pragma unroll
        for (int e = 0; e < NE; e++) { ex[e] = expf(logit[e] - mx); s += ex[e]; }
        float inv = 1.f / s;
#pragma unroll
        for (int e = 0; e < NE; e++) g_gates[gwarp * NE + e] = ex[e] * inv;

        int i0 = 0;
#pragma unroll
        for (int e = 1; e < NE; e++) if (logit[e] > logit[i0]) i0 = e;
        int i1 = -1;
#pragma unroll
        for (int e = 0; e < NE; e++)
            if (e != i0 && (i1 < 0 || logit[e] > logit[i1])) i1 = e;

        float w0 = 1.f / (1.f + expf(logit[i1] - logit[i0]));
        g_topi[gwarp * 2 + 0] = i0;
        g_topi[gwarp * 2 + 1] = i1;
        g_topw[gwarp * 2 + 0] = w0;
        g_topw[gwarp * 2 + 1] = 1.f - w0;
    }
}

__global__ void route_kernel() {
    __shared__ int hist[RT_THREADS][NE];
    __shared__ int offs_sh[NE];
    __shared__ int counts_sh[NE];
    int tid = threadIdx.x;

    int h[NE];
#pragma unroll
    for (int e = 0; e < NE; e++) h[e] = 0;
    int t0 = tid * TOK_PER_TH;
    for (int i = 0; i < TOK_PER_TH; i++) {
        int t = t0 + i;
        h[g_topi[t * 2 + 0]]++;
        h[g_topi[t * 2 + 1]]++;
    }
#pragma unroll
    for (int e = 0; e < NE; e++) hist[tid][e] = h[e];
    __syncthreads();

    if (tid < NE) {
        int e = tid, s = 0;
        for (int j = 0; j < RT_THREADS; j++) {
            int v = hist[j][e];
            hist[j][e] = s;
            s += v;
        }
        counts_sh[e] = s;
        g_counts[e]  = s;
    }
    __syncthreads();

    if (tid == 0) {
        int off = 0;
        for (int e = 0; e < NE; e++) { offs_sh[e] = off; off += counts_sh[e]; }
    }
    __syncthreads();

    int base[NE];
#pragma unroll
    for (int e = 0; e < NE; e++) base[e] = offs_sh[e] + hist[tid][e];

    for (int i = 0; i < TOK_PER_TH; i++) {
        int t = t0 + i;
#pragma unroll
        for (int k = 0; k < TOPK; k++) {
            int e   = g_topi[t * 2 + k];
            int row = base[e]++;
            g_token_of_row[row] = t;
            g_wt_of_row[row]    = g_topw[t * 2 + k];
        }
    }
}

// Zero the token-output region (fused-combine accumulates into it).
__global__ void zero_out_kernel(float* __restrict__ out) {
    int i = blockIdx.x * blockDim.x + threadIdx.x;
    if (i < BTOK * DOUT) out[i] = 0.f;
}

// Fused per-expert usage mean + load-balance loss (single block, deterministic).
__global__ void usage_loss_kernel(float* __restrict__ out, int out_size) {
    __shared__ float s[256][NE];
    int tid = threadIdx.x;
    float acc[NE];
#pragma unroll
    for (int e = 0; e < NE; e++) acc[e] = 0.f;
    for (int t = tid; t < BTOK; t += 256) {
        const float* g = g_gates + (size_t)t * NE;
#pragma unroll
        for (int e = 0; e < NE; e++) acc[e] += g[e];
    }
#pragma unroll
    for (int e = 0; e < NE; e++) s[tid][e] = acc[e];
    __syncthreads();
    if (tid == 0) {
        float loss = 0.f;
        for (int e = 0; e < NE; e++) {
            float u = 0.f;
            for (int j = 0; j < 256; j++) u += s[j][e];
            u /= (float)BTOK;
            loss += u * u;
        }
        if (out_size > BTOK * DOUT) out[BTOK * DOUT] = (float)NE * loss;
    }
}

// ---------------- grouped GEMM: cp.async (3-stage, BK=64) + fp16 HMMA -----------
// 256 threads, 8 warps (4m x 2n), warp tile 32x64, 2 CTAs/SM (16 warps).
// STAGE=1: A = g_xh (gathered rows) -> g_hh (fp16x2), ReLU.
// STAGE=2: A = g_hh (contiguous)    -> atomicAdd into out (fused combine).
template <int KD, int ND, int STAGE>
__global__ void __launch_bounds__(256, 2)
moe_gemm_f16(const float* __restrict__ bias, float* __restrict__ out) {
    int t = blockIdx.x;

    int e = 0, grow0 = 0, rows = 0;
    {
        int tileacc = 0, off = 0;
        bool found = false;
#pragma unroll
        for (int ee = 0; ee < NE; ee++) {
            int c  = g_counts[ee];
            int nt = (c + BM - 1) / BM;
            if (!found && t < tileacc + nt) {
                found = true;
                e     = ee;
                int rb = (t - tileacc) * BM;
                grow0 = off + rb;
                rows  = min(BM, c - rb);
            }
            tileacc += nt;
            off     += c;
        }
        if (!found) return;
    }
    int n0 = blockIdx.y * BN;

    extern __shared__ __align__(16) uint8_t dynsmem[];
    uint32_t sbase = smem_u32(dynsmem);

    int tid = threadIdx.x, wid = tid >> 5, lane = tid & 31;
    int warp_m = wid & 3;        // 0..3 -> m offset *32
    int warp_n = wid >> 2;       // 0..1 -> n offset *64

    // ---- cp.async source pointers ----
    int arow = tid >> 1, ahalf = tid & 1;           // A: 128 rows x 2 64B-halves
    const uint32_t* Asrc;
    if (STAGE == 1) {
        int tok = (arow < rows) ? g_token_of_row[grow0 + arow] : g_token_of_row[grow0];
        Asrc = g_xh + (size_t)tok * (KD / 2);
    } else {
        int r = min(grow0 + arow, MAXROWS - 1);
        Asrc = g_hh + (size_t)r * (KD / 2);
    }
    int bkrow = tid >> 2, bseg = tid & 3;           // B: 64 k-rows x 4 64B-segs
    const uint32_t* Wsrc = (STAGE == 1 ? g_w1h : g_w2h)
                           + ((size_t)e * KD + bkrow) * (ND / 2) + n0 / 2 + bseg * 16;

    // ---- ldmatrix address bases ----
    uint32_t a_off = (uint32_t)(warp_m * 32 + (lane & 15)) * A_STRIDE
                   + (uint32_t)(lane >> 4) * 16;
    uint32_t b_off = (uint32_t)((lane & 7) + ((lane >> 3) & 1) * 8) * B_STRIDE
                   + (uint32_t)(warp_n * 64 + ((lane >> 4) & 1) * 8) * 2;

    float acc[2][8][4];
#pragma unroll
    for (int i = 0; i < 2; i++)
#pragma unroll
        for (int j = 0; j < 8; j++)
#pragma unroll
            for (int q = 0; q < 4; q++) acc[i][j][q] = 0.f;

    const int NCH = KD / BK;

    auto issue = [&](int it) {
        uint32_t base = sbase + (uint32_t)(it % NSTAGE) * STG_BYTES;
        int k0 = it * BK;
        // A: row arow, 64B half -> 4x16B
        uint32_t dA = base + (uint32_t)arow * A_STRIDE + (uint32_t)ahalf * 64;
        const uint32_t* sa = Asrc + (k0 >> 1) + ahalf * 16;
        cp16(dA,      sa);
        cp16(dA + 16, sa + 4);
        cp16(dA + 32, sa + 8);
        cp16(dA + 48, sa + 12);
        // B: k-row bkrow, 64B seg -> 4x16B
        uint32_t dB = base + A_REG + (uint32_t)bkrow * B_STRIDE + (uint32_t)bseg * 64;
        const uint32_t* sb = Wsrc + (size_t)k0 * (ND / 2);
        cp16(dB,      sb);
        cp16(dB + 16, sb + 4);
        cp16(dB + 32, sb + 8);
        cp16(dB + 48, sb + 12);
        CP_COMMIT();
    };

    // prologue: 2 chunks in flight
    issue(0);
    issue(1);

    for (int it = 0; it < NCH; it++) {
        if (it < NCH - 1) CP_WAIT1(); else CP_WAIT0();
        __syncthreads();
        // refill slot (it+2)%3 == (it-1)%3, consumed before the barrier above
        if (it + 2 < NCH) issue(it + 2);

        uint32_t base = sbase + (uint32_t)(it % NSTAGE) * STG_BYTES;
        uint32_t Ab = base, Bb = base + A_REG;

#pragma unroll
        for (int h = 0; h < 4; h++) {      // 4 k-steps of 16 per BK=64 chunk
            uint32_t fA[2][4];
#pragma unroll
            for (int mi = 0; mi < 2; mi++)
                ldsm4(fA[mi], Ab + a_off + (uint32_t)mi * (16 * A_STRIDE)
                                         + (uint32_t)h * 32);
#pragma unroll
            for (int n2 = 0; n2 < 4; n2++) {
                uint32_t fB[4];
                ldsm4t(fB, Bb + b_off + (uint32_t)h * (16 * B_STRIDE)
                                      + (uint32_t)n2 * 32);
#pragma unroll
                for (int mi = 0; mi < 2; mi++) {
                    mma_f16(acc[mi][2 * n2],     fA[mi], fB[0], fB[1]);
                    mma_f16(acc[mi][2 * n2 + 1], fA[mi], fB[2], fB[3]);
                }
            }
        }
    }

    // ---- epilogue ----
#pragma unroll
    for (int mi = 0; mi < 2; mi++) {
        int m_lo = warp_m * 32 + mi * 16 + (lane >> 2);
#pragma unroll
        for (int ni = 0; ni < 8; ni++) {
            int ncol = warp_n * 64 + ni * 8 + 2 * (lane & 3);
            float b0 = bias[(size_t)e * ND + n0 + ncol];
            float b1 = bias[(size_t)e * ND + n0 + ncol + 1];
#pragma unroll
            for (int half = 0; half < 2; half++) {
                int m = m_lo + half * 8;
                if (m < rows) {
                    float v0 = acc[mi][ni][2 * half]     + b0;
                    float v1 = acc[mi][ni][2 * half + 1] + b1;
                    size_t grow = (size_t)(grow0 + m);
                    if (STAGE == 1) {
                        v0 = fmaxf(v0, 0.f);
                        v1 = fmaxf(v1, 0.f);
                        g_hh[grow * (ND / 2) + (size_t)(n0 + ncol) / 2] =
                            h2u(__floats2half2_rn(v0, v1));
                    } else {
                        // fused combine: out[token] += w * y  (2 adds/elem, IEEE-
                        // commutative onto zeroed slots -> bit-deterministic)
                        int   tok = g_token_of_row[grow];
                        float w   = g_wt_of_row[grow];
                        float* op = out + (size_t)tok * ND + n0 + ncol;
                        atomicAdd(op,     w * v0);
                        atomicAdd(op + 1, w * v1);
                    }
                }
            }
        }
    }
}

// ---------------- launch ---------------------------------------------------------

extern "C" void kernel_launch(void* const* d_in, const int* in_sizes, int n_in,
                              void* d_out, int out_size) {
    const float *x = 0, *Wg = 0, *bg = 0, *W1 = 0, *b1 = 0, *W2 = 0, *b2 = 0;
    for (int i = 0; i < n_in; i++) {
        const float* p = (const float*)d_in[i];
        switch (in_sizes[i]) {
            case BTOK * DIN:        x  = p; break;                        // 4194304
            case NE:                bg = p; break;                        // 8
            case NE * DHID:         b1 = p; break;                        // 32768
            case NE * DIN * DHID:   if (!W1) W1 = p; else W2 = p; break;  // 33554432
            case DIN * NE:          if (!Wg) Wg = p; else b2 = p; break;  // 8192
            default: break;
        }
    }
    if (!(x && Wg && bg && W1 && b1 && W2 && b2)) {
        x  = (const float*)d_in[0]; Wg = (const float*)d_in[1];
        bg = (const float*)d_in[2]; W1 = (const float*)d_in[3];
        b1 = (const float*)d_in[4]; W2 = (const float*)d_in[5];
        b2 = (const float*)d_in[6];
    }
    float* out = (float*)d_out;

    cudaFuncSetAttribute(moe_gemm_f16<DIN, DHID, 1>,
                         cudaFuncAttributeMaxDynamicSharedMemorySize, SMEM_TOTAL);
    cudaFuncSetAttribute(moe_gemm_f16<DHID, DOUT, 2>,
                         cudaFuncAttributeMaxDynamicSharedMemorySize, SMEM_TOTAL);

    convert_all_kernel<<<(int)((ALLQUADS + 255) / 256), 256>>>(x, W1, W2); // 1
    gating_kernel<<<BTOK / 8, 256>>>(x, Wg, bg);                           // 2
    route_kernel<<<1, RT_THREADS>>>();                                     // 3

    moe_gemm_f16<DIN, DHID, 1>                                             // 4 (ncu)
        <<<dim3(MAXTILES, DHID / BN), 256, SMEM_TOTAL>>>(b1, nullptr);

    zero_out_kernel<<<(BTOK * DOUT + 255) / 256, 256>>>(out);              // 5
    usage_loss_kernel<<<1, 256>>>(out, out_size);                          // 6

    moe_gemm_f16<DHID, DOUT, 2>                                            // 7
        <<<dim3(MAXTILES, DOUT / BN), 256, SMEM_TOTAL>>>(b2, out);
}

// round 15
// speedup vs baseline: 1.3348x; 1.2046x over previous
#include <cuda_runtime.h>
#include <cuda_fp16.h>
#include <math.h>
#include <stdint.h>

// ---------------- problem constants -------------------------------------------
#define BTOK   4096
#define DIN    1024
#define DHID   4096
#define DOUT   1024
#define NE     8
#define TOPK   2
#define MAXROWS (BTOK * TOPK)          // 8192 grouped rows, always exact
#define BM     128
#define BN     128
#define BK     32
#define MAXTILES (MAXROWS / BM + NE)   // 72 worst-case m-tiles

#define RT_THREADS 256
#define TOK_PER_TH (BTOK / RT_THREADS) // 16

// ---------------- smem tile geometry (R11-proven) --------------------------------
#define A_STRIDE 80                     // bytes per A row: 32 fp16 (64B) + 16B pad
#define B_STRIDE 272                    // bytes per B k-row: 128 fp16 (256B) + 16B pad
#define A_REG (BM * A_STRIDE)           // 10240
#define B_REG (BK * B_STRIDE)           // 8704
#define STG_BYTES (A_REG + B_REG)       // 18944 per stage
#define NSTAGE 4
#define SMEM_TOTAL (NSTAGE * STG_BYTES) // 75776 (2 CTAs/SM)

// quad counts for the fused fp32->fp16 conversion (4 floats -> 2 words each)
#define XQUADS (BTOK * (size_t)DIN / 4)
#define WQUADS ((size_t)NE * DIN * DHID / 4)
#define ALLQUADS (XQUADS + 2 * WQUADS)       // 17,825,792

// ---------------- device scratch (device-code-only access!) --------------------
__device__ uint32_t g_xh[BTOK * (size_t)(DIN / 2)];          // fp16x2
__device__ uint32_t g_w1h[(size_t)NE * DIN * DHID / 2];
__device__ uint32_t g_w2h[(size_t)NE * DHID * DOUT / 2];
__device__ uint32_t g_hh[MAXROWS * (size_t)(DHID / 2)];
__device__ float    g_gates[BTOK * NE];
__device__ float    g_topw[BTOK * TOPK];
__device__ int      g_topi[BTOK * TOPK];
__device__ int      g_counts[NE];
__device__ int      g_token_of_row[MAXROWS];
__device__ float    g_wt_of_row[MAXROWS];

// ---------------- helpers -------------------------------------------------------
__device__ __forceinline__ uint32_t smem_u32(const void* p) {
    uint32_t a;
    asm("{ .reg .u64 t; cvta.to.shared.u64 t, %1; cvt.u32.u64 %0, t; }"
        : "=r"(a) : "l"(p));
    return a;
}

__device__ __forceinline__ void ldsm4(uint32_t* r, uint32_t addr) {
    asm volatile("ldmatrix.sync.aligned.m8n8.x4.shared.b16 {%0,%1,%2,%3}, [%4];"
                 : "=r"(r[0]), "=r"(r[1]), "=r"(r[2]), "=r"(r[3]) : "r"(addr));
}

__device__ __forceinline__ void ldsm4t(uint32_t* r, uint32_t addr) {
    asm volatile("ldmatrix.sync.aligned.m8n8.x4.trans.shared.b16 {%0,%1,%2,%3}, [%4];"
                 : "=r"(r[0]), "=r"(r[1]), "=r"(r[2]), "=r"(r[3]) : "r"(addr));
}

__device__ __forceinline__ void mma_f16(float* c, const uint32_t* a,
                                        uint32_t b0, uint32_t b1) {
    asm volatile(
        "mma.sync.aligned.m16n8k16.row.col.f32.f16.f16.f32 "
        "{%0,%1,%2,%3}, {%4,%5,%6,%7}, {%8,%9}, {%0,%1,%2,%3};"
        : "+f"(c[0]), "+f"(c[1]), "+f"(c[2]), "+f"(c[3])
        : "r"(a[0]), "r"(a[1]), "r"(a[2]), "r"(a[3]), "r"(b0), "r"(b1));
}

__device__ __forceinline__ void cp16(uint32_t dst, const void* src) {
    asm volatile("cp.async.cg.shared.global [%0], [%1], 16;"
                 :: "r"(dst), "l"(src));
}
#define CP_COMMIT() asm volatile("cp.async.commit_group;" ::: "memory")
#define CP_WAIT2()  asm volatile("cp.async.wait_group 2;" ::: "memory")
#define CP_WAIT1()  asm volatile("cp.async.wait_group 1;" ::: "memory")
#define CP_WAIT0()  asm volatile("cp.async.wait_group 0;" ::: "memory")

__device__ __forceinline__ uint32_t h2u(__half2 h) {
    return *reinterpret_cast<uint32_t*>(&h);
}

// ---------------- fused convert: x, W1, W2 -> fp16 ------------------------------
__global__ void convert_all_kernel(const float* __restrict__ x,
                                   const float* __restrict__ W1,
                                   const float* __restrict__ W2) {
    size_t p = (size_t)blockIdx.x * blockDim.x + threadIdx.x;
    if (p >= ALLQUADS) return;
    const float* src;
    uint32_t* dst;
    size_t q;
    if (p < XQUADS)               { q = p;                    src = x;  dst = g_xh;  }
    else if (p < XQUADS + WQUADS) { q = p - XQUADS;           src = W1; dst = g_w1h; }
    else                          { q = p - XQUADS - WQUADS;  src = W2; dst = g_w2h; }
    float4 v = ((const float4*)src)[q];
    dst[q * 2 + 0] = h2u(__floats2half2_rn(v.x, v.y));
    dst[q * 2 + 1] = h2u(__floats2half2_rn(v.z, v.w));
}

// ---------------- gating / routing / loss --------------------------------------

__global__ void gating_kernel(const float* __restrict__ x,
                              const float* __restrict__ Wg,
                              const float* __restrict__ bg) {
    int gwarp = (blockIdx.x * blockDim.x + threadIdx.x) >> 5;
    int lane  = threadIdx.x & 31;
    if (gwarp >= BTOK) return;
    const float* xr = x + (size_t)gwarp * DIN;

    float acc[NE];
#pragma unroll
    for (int e = 0; e < NE; e++) acc[e] = 0.f;

    for (int i = lane; i < DIN; i += 32) {
        float xv = xr[i];
        const float4* wg4 = (const float4*)(Wg + (size_t)i * NE);
        float4 w0 = wg4[0];
        float4 w1 = wg4[1];
        acc[0] += xv * w0.x; acc[1] += xv * w0.y;
        acc[2] += xv * w0.z; acc[3] += xv * w0.w;
        acc[4] += xv * w1.x; acc[5] += xv * w1.y;
        acc[6] += xv * w1.z; acc[7] += xv * w1.w;
    }
#pragma unroll
    for (int e = 0; e < NE; e++)
#pragma unroll
        for (int o = 16; o > 0; o >>= 1)
            acc[e] += __shfl_xor_sync(0xffffffffu, acc[e], o);

    if (lane == 0) {
        float logit[NE];
#pragma unroll
        for (int e = 0; e < NE; e++) logit[e] = acc[e] + bg[e];

        float mx = logit[0];
#pragma unroll
        for (int e = 1; e < NE; e++) mx = fmaxf(mx, logit[e]);
        float s = 0.f, ex[NE];
#pragma unroll
        for (int e = 0; e < NE; e++) { ex[e] = expf(logit[e] - mx); s += ex[e]; }
        float inv = 1.f / s;
#pragma unroll
        for (int e = 0; e < NE; e++) g_gates[gwarp * NE + e] = ex[e] * inv;

        int i0 = 0;
#pragma unroll
        for (int e = 1; e < NE; e++) if (logit[e] > logit[i0]) i0 = e;
        int i1 = -1;
#pragma unroll
        for (int e = 0; e < NE; e++)
            if (e != i0 && (i1 < 0 || logit[e] > logit[i1])) i1 = e;

        float w0 = 1.f / (1.f + expf(logit[i1] - logit[i0]));
        g_topi[gwarp * 2 + 0] = i0;
        g_topi[gwarp * 2 + 1] = i1;
        g_topw[gwarp * 2 + 0] = w0;
        g_topw[gwarp * 2 + 1] = 1.f - w0;
    }
}

__global__ void route_kernel() {
    __shared__ int hist[RT_THREADS][NE];
    __shared__ int offs_sh[NE];
    __shared__ int counts_sh[NE];
    int tid = threadIdx.x;

    int h[NE];
#pragma unroll
    for (int e = 0; e < NE; e++) h[e] = 0;
    int t0 = tid * TOK_PER_TH;
    for (int i = 0; i < TOK_PER_TH; i++) {
        int t = t0 + i;
        h[g_topi[t * 2 + 0]]++;
        h[g_topi[t * 2 + 1]]++;
    }
#pragma unroll
    for (int e = 0; e < NE; e++) hist[tid][e] = h[e];
    __syncthreads();

    if (tid < NE) {
        int e = tid, s = 0;
        for (int j = 0; j < RT_THREADS; j++) {
            int v = hist[j][e];
            hist[j][e] = s;
            s += v;
        }
        counts_sh[e] = s;
        g_counts[e]  = s;
    }
    __syncthreads();

    if (tid == 0) {
        int off = 0;
        for (int e = 0; e < NE; e++) { offs_sh[e] = off; off += counts_sh[e]; }
    }
    __syncthreads();

    int base[NE];
#pragma unroll
    for (int e = 0; e < NE; e++) base[e] = offs_sh[e] + hist[tid][e];

    for (int i = 0; i < TOK_PER_TH; i++) {
        int t = t0 + i;
#pragma unroll
        for (int k = 0; k < TOPK; k++) {
            int e   = g_topi[t * 2 + k];
            int row = base[e]++;
            g_token_of_row[row] = t;
            g_wt_of_row[row]    = g_topw[t * 2 + k];
        }
    }
}

// Zero the token-output region (fused-combine accumulates into it).
__global__ void zero_out_kernel(float* __restrict__ out) {
    int i = blockIdx.x * blockDim.x + threadIdx.x;
    if (i < BTOK * DOUT) out[i] = 0.f;
}

// Fused per-expert usage mean + load-balance loss (single block, deterministic).
__global__ void usage_loss_kernel(float* __restrict__ out, int out_size) {
    __shared__ float s[256][NE];
    int tid = threadIdx.x;
    float acc[NE];
#pragma unroll
    for (int e = 0; e < NE; e++) acc[e] = 0.f;
    for (int t = tid; t < BTOK; t += 256) {
        const float* g = g_gates + (size_t)t * NE;
#pragma unroll
        for (int e = 0; e < NE; e++) acc[e] += g[e];
    }
#pragma unroll
    for (int e = 0; e < NE; e++) s[tid][e] = acc[e];
    __syncthreads();
    if (tid == 0) {
        float loss = 0.f;
        for (int e = 0; e < NE; e++) {
            float u = 0.f;
            for (int j = 0; j < 256; j++) u += s[j][e];
            u /= (float)BTOK;
            loss += u * u;
        }
        if (out_size > BTOK * DOUT) out[BTOK * DOUT] = (float)NE * loss;
    }
}

// ---------------- grouped GEMM: cp.async (4-stage) + fp16 HMMA (R11 config) -----
// STAGE=1: A = g_xh (gathered rows) -> g_hh (fp16x2), ReLU.
// STAGE=2: A = g_hh (contiguous)    -> atomicAdd into out (fused combine).
template <int KD, int ND, int STAGE>
__global__ void __launch_bounds__(256, 2)
moe_gemm_f16(const float* __restrict__ bias, float* __restrict__ out) {
    int t = blockIdx.x;

    int e = 0, grow0 = 0, rows = 0;
    {
        int tileacc = 0, off = 0;
        bool found = false;
#pragma unroll
        for (int ee = 0; ee < NE; ee++) {
            int c  = g_counts[ee];
            int nt = (c + BM - 1) / BM;
            if (!found && t < tileacc + nt) {
                found = true;
                e     = ee;
                int rb = (t - tileacc) * BM;
                grow0 = off + rb;
                rows  = min(BM, c - rb);
            }
            tileacc += nt;
            off     += c;
        }
        if (!found) return;
    }
    int n0 = blockIdx.y * BN;

    extern __shared__ __align__(16) uint8_t dynsmem[];
    uint32_t sbase = smem_u32(dynsmem);

    int tid = threadIdx.x, wid = tid >> 5, lane = tid & 31;
    int warp_m = wid & 3;        // 0..3 -> m offset *32
    int warp_n = wid >> 2;       // 0..1 -> n offset *64

    // ---- cp.async source pointers ----
    int arow = tid >> 1, ahalf = tid & 1;           // A: 128 rows x 2 halves
    const uint32_t* Asrc;
    if (STAGE == 1) {
        int tok = (arow < rows) ? g_token_of_row[grow0 + arow] : g_token_of_row[grow0];
        Asrc = g_xh + (size_t)tok * (KD / 2);
    } else {
        int r = min(grow0 + arow, MAXROWS - 1);
        Asrc = g_hh + (size_t)r * (KD / 2);
    }
    int bkrow = tid >> 3, bseg = tid & 7;           // B: 32 k-rows x 8 segs x2
    const uint32_t* Wsrc = (STAGE == 1 ? g_w1h : g_w2h)
                           + ((size_t)e * KD + bkrow) * (ND / 2) + n0 / 2 + bseg * 4;

    // ---- ldmatrix address bases ----
    uint32_t a_off = (uint32_t)(warp_m * 32 + (lane & 15)) * A_STRIDE
                   + (uint32_t)(lane >> 4) * 16;
    uint32_t b_off = (uint32_t)((lane & 7) + ((lane >> 3) & 1) * 8) * B_STRIDE
                   + (uint32_t)(warp_n * 64 + ((lane >> 4) & 1) * 8) * 2;

    float acc[2][8][4];
#pragma unroll
    for (int i = 0; i < 2; i++)
#pragma unroll
        for (int j = 0; j < 8; j++)
#pragma unroll
            for (int q = 0; q < 4; q++) acc[i][j][q] = 0.f;

    const int NCH = KD / BK;

    auto issue = [&](int it) {
        uint32_t base = sbase + (uint32_t)(it & (NSTAGE - 1)) * STG_BYTES;
        int k0 = it * BK;
        uint32_t dA = base + (uint32_t)arow * A_STRIDE + (uint32_t)ahalf * 32;
        const uint32_t* sa = Asrc + (k0 >> 1) + ahalf * 8;
        cp16(dA,      sa);
        cp16(dA + 16, sa + 4);
        uint32_t dB = base + A_REG + (uint32_t)bkrow * B_STRIDE + (uint32_t)bseg * 16;
        const uint32_t* sb = Wsrc + (size_t)k0 * (ND / 2);
        cp16(dB,       sb);
        cp16(dB + 128, sb + 32);
        CP_COMMIT();
    };

    // prologue: 3 chunks in flight
    issue(0);
    issue(1);
    issue(2);

    for (int it = 0; it < NCH; it++) {
        if (it < NCH - 2)       CP_WAIT2();
        else if (it == NCH - 2) CP_WAIT1();
        else                    CP_WAIT0();
        __syncthreads();
        // refill the slot consumed 2 syncs ago (race-free after the sync above)
        if (it + 3 < NCH) issue(it + 3);

        uint32_t base = sbase + (uint32_t)(it & (NSTAGE - 1)) * STG_BYTES;
        uint32_t Ab = base, Bb = base + A_REG;

#pragma unroll
        for (int h = 0; h < 2; h++) {
            uint32_t fA[2][4];
#pragma unroll
            for (int mi = 0; mi < 2; mi++) {
                uint32_t ad = a_off + (uint32_t)mi * (16 * A_STRIDE) + (uint32_t)h * 32;
                ldsm4(fA[mi], Ab + ad);
            }
#pragma unroll
            for (int n2 = 0; n2 < 4; n2++) {
                uint32_t fB[4];
                uint32_t bd = b_off + (uint32_t)h * (16 * B_STRIDE) + (uint32_t)n2 * 32;
                ldsm4t(fB, Bb + bd);
#pragma unroll
                for (int mi = 0; mi < 2; mi++) {
                    mma_f16(acc[mi][2 * n2],     fA[mi], fB[0], fB[1]);
                    mma_f16(acc[mi][2 * n2 + 1], fA[mi], fB[2], fB[3]);
                }
            }
        }
    }

    // ---- epilogue ----
#pragma unroll
    for (int mi = 0; mi < 2; mi++) {
        int m_lo = warp_m * 32 + mi * 16 + (lane >> 2);
#pragma unroll
        for (int ni = 0; ni < 8; ni++) {
            int ncol = warp_n * 64 + ni * 8 + 2 * (lane & 3);
            float b0 = bias[(size_t)e * ND + n0 + ncol];
            float b1 = bias[(size_t)e * ND + n0 + ncol + 1];
#pragma unroll
            for (int half = 0; half < 2; half++) {
                int m = m_lo + half * 8;
                if (m < rows) {
                    float v0 = acc[mi][ni][2 * half]     + b0;
                    float v1 = acc[mi][ni][2 * half + 1] + b1;
                    size_t grow = (size_t)(grow0 + m);
                    if (STAGE == 1) {
                        v0 = fmaxf(v0, 0.f);
                        v1 = fmaxf(v1, 0.f);
                        g_hh[grow * (ND / 2) + (size_t)(n0 + ncol) / 2] =
                            h2u(__floats2half2_rn(v0, v1));
                    } else {
                        // fused combine: out[token] += w * y  (2 adds/elem, IEEE-
                        // commutative onto zeroed slots -> bit-deterministic)
                        int   tok = g_token_of_row[grow];
                        float w   = g_wt_of_row[grow];
                        float* op = out + (size_t)tok * ND + n0 + ncol;
                        atomicAdd(op,     w * v0);
                        atomicAdd(op + 1, w * v1);
                    }
                }
            }
        }
    }
}

// ---------------- launch ---------------------------------------------------------

extern "C" void kernel_launch(void* const* d_in, const int* in_sizes, int n_in,
                              void* d_out, int out_size) {
    const float *x = 0, *Wg = 0, *bg = 0, *W1 = 0, *b1 = 0, *W2 = 0, *b2 = 0;
    for (int i = 0; i < n_in; i++) {
        const float* p = (const float*)d_in[i];
        switch (in_sizes[i]) {
            case BTOK * DIN:        x  = p; break;                        // 4194304
            case NE:                bg = p; break;                        // 8
            case NE * DHID:         b1 = p; break;                        // 32768
            case NE * DIN * DHID:   if (!W1) W1 = p; else W2 = p; break;  // 33554432
            case DIN * NE:          if (!Wg) Wg = p; else b2 = p; break;  // 8192
            default: break;
        }
    }
    if (!(x && Wg && bg && W1 && b1 && W2 && b2)) {
        x  = (const float*)d_in[0]; Wg = (const float*)d_in[1];
        bg = (const float*)d_in[2]; W1 = (const float*)d_in[3];
        b1 = (const float*)d_in[4]; W2 = (const float*)d_in[5];
        b2 = (const float*)d_in[6];
    }
    float* out = (float*)d_out;

    cudaFuncSetAttribute(moe_gemm_f16<DIN, DHID, 1>,
                         cudaFuncAttributeMaxDynamicSharedMemorySize, SMEM_TOTAL);
    cudaFuncSetAttribute(moe_gemm_f16<DHID, DOUT, 2>,
                         cudaFuncAttributeMaxDynamicSharedMemorySize, SMEM_TOTAL);

    convert_all_kernel<<<(int)((ALLQUADS + 255) / 256), 256>>>(x, W1, W2); // 1
    gating_kernel<<<BTOK / 8, 256>>>(x, Wg, bg);                           // 2
    route_kernel<<<1, RT_THREADS>>>();                                     // 3

    moe_gemm_f16<DIN, DHID, 1>                                             // 4 (ncu)
        <<<dim3(MAXTILES, DHID / BN), 256, SMEM_TOTAL>>>(b1, nullptr);

    zero_out_kernel<<<(BTOK * DOUT + 255) / 256, 256>>>(out);              // 5
    usage_loss_kernel<<<1, 256>>>(out, out_size);                          // 6

    moe_gemm_f16<DHID, DOUT, 2>                                            // 7
        <<<dim3(MAXTILES, DOUT / BN), 256, SMEM_TOTAL>>>(b2, out);
}

// round 16
// speedup vs baseline: 1.3405x; 1.0043x over previous
#include <cuda_runtime.h>
#include <cuda_fp16.h>
#include <math.h>
#include <stdint.h>

// ---------------- problem constants -------------------------------------------
#define BTOK   4096
#define DIN    1024
#define DHID   4096
#define DOUT   1024
#define NE     8
#define TOPK   2
#define MAXROWS (BTOK * TOPK)          // 8192 grouped rows, always exact
#define BM     128
#define BN     128
#define BK     32
#define MAXTILES (MAXROWS / BM + NE)   // 72 worst-case m-tiles

#define RT_THREADS 256
#define TOK_PER_TH (BTOK / RT_THREADS) // 16

// ---------------- smem tile geometry (R11-proven) --------------------------------
#define A_STRIDE 80                     // bytes per A row: 32 fp16 (64B) + 16B pad
#define B_STRIDE 272                    // bytes per B k-row: 128 fp16 (256B) + 16B pad
#define A_REG (BM * A_STRIDE)           // 10240
#define B_REG (BK * B_STRIDE)           // 8704
#define STG_BYTES (A_REG + B_REG)       // 18944 per stage
#define NSTAGE 4
#define SMEM_TOTAL (NSTAGE * STG_BYTES) // 75776 (2 CTAs/SM)

// work ranges for the fused W-convert + out-zero kernel
#define WQUADS ((size_t)NE * DIN * DHID / 4)   // 8,388,608 per W
#define ZQUADS ((size_t)BTOK * DOUT / 4)       // 1,048,576
#define FUSED_ITEMS (2 * WQUADS + ZQUADS)      // 17,825,792

// ---------------- device scratch (device-code-only access!) --------------------
__device__ uint32_t g_xh[BTOK * (size_t)(DIN / 2)];          // fp16x2
__device__ uint32_t g_w1h[(size_t)NE * DIN * DHID / 2];
__device__ uint32_t g_w2h[(size_t)NE * DHID * DOUT / 2];
__device__ uint32_t g_hh[MAXROWS * (size_t)(DHID / 2)];
__device__ float    g_gates[BTOK * NE];
__device__ float    g_topw[BTOK * TOPK];
__device__ int      g_topi[BTOK * TOPK];
__device__ int      g_counts[NE];
__device__ int      g_token_of_row[MAXROWS];
__device__ float    g_wt_of_row[MAXROWS];

// ---------------- helpers -------------------------------------------------------
__device__ __forceinline__ uint32_t smem_u32(const void* p) {
    uint32_t a;
    asm("{ .reg .u64 t; cvta.to.shared.u64 t, %1; cvt.u32.u64 %0, t; }"
        : "=r"(a) : "l"(p));
    return a;
}

__device__ __forceinline__ void ldsm4(uint32_t* r, uint32_t addr) {
    asm volatile("ldmatrix.sync.aligned.m8n8.x4.shared.b16 {%0,%1,%2,%3}, [%4];"
                 : "=r"(r[0]), "=r"(r[1]), "=r"(r[2]), "=r"(r[3]) : "r"(addr));
}

__device__ __forceinline__ void ldsm4t(uint32_t* r, uint32_t addr) {
    asm volatile("ldmatrix.sync.aligned.m8n8.x4.trans.shared.b16 {%0,%1,%2,%3}, [%4];"
                 : "=r"(r[0]), "=r"(r[1]), "=r"(r[2]), "=r"(r[3]) : "r"(addr));
}

__device__ __forceinline__ void mma_f16(float* c, const uint32_t* a,
                                        uint32_t b0, uint32_t b1) {
    asm volatile(
        "mma.sync.aligned.m16n8k16.row.col.f32.f16.f16.f32 "
        "{%0,%1,%2,%3}, {%4,%5,%6,%7}, {%8,%9}, {%0,%1,%2,%3};"
        : "+f"(c[0]), "+f"(c[1]), "+f"(c[2]), "+f"(c[3])
        : "r"(a[0]), "r"(a[1]), "r"(a[2]), "r"(a[3]), "r"(b0), "r"(b1));
}

__device__ __forceinline__ void cp16(uint32_t dst, const void* src) {
    asm volatile("cp.async.cg.shared.global [%0], [%1], 16;"
                 :: "r"(dst), "l"(src));
}
#define CP_COMMIT() asm volatile("cp.async.commit_group;" ::: "memory")
#define CP_WAIT2()  asm volatile("cp.async.wait_group 2;" ::: "memory")
#define CP_WAIT1()  asm volatile("cp.async.wait_group 1;" ::: "memory")
#define CP_WAIT0()  asm volatile("cp.async.wait_group 0;" ::: "memory")

__device__ __forceinline__ uint32_t h2u(__half2 h) {
    return *reinterpret_cast<uint32_t*>(&h);
}

// ---------------- fused gating + x->fp16 convert --------------------------------
// One warp per token: gate logits, full softmax (for loss), top-2 + weights,
// and convert the token's x row to fp16 (row is L1-hot from the logit pass).
__global__ void gating_kernel(const float* __restrict__ x,
                              const float* __restrict__ Wg,
                              const float* __restrict__ bg) {
    int gwarp = (blockIdx.x * blockDim.x + threadIdx.x) >> 5;
    int lane  = threadIdx.x & 31;
    if (gwarp >= BTOK) return;
    const float* xr = x + (size_t)gwarp * DIN;

    float acc[NE];
#pragma unroll
    for (int e = 0; e < NE; e++) acc[e] = 0.f;

    for (int i = lane; i < DIN; i += 32) {
        float xv = xr[i];
        const float4* wg4 = (const float4*)(Wg + (size_t)i * NE);
        float4 w0 = wg4[0];
        float4 w1 = wg4[1];
        acc[0] += xv * w0.x; acc[1] += xv * w0.y;
        acc[2] += xv * w0.z; acc[3] += xv * w0.w;
        acc[4] += xv * w1.x; acc[5] += xv * w1.y;
        acc[6] += xv * w1.z; acc[7] += xv * w1.w;
    }
#pragma unroll
    for (int e = 0; e < NE; e++)
#pragma unroll
        for (int o = 16; o > 0; o >>= 1)
            acc[e] += __shfl_xor_sync(0xffffffffu, acc[e], o);

    // convert this token's row to fp16 (all lanes)
    {
        const float2* xr2 = (const float2*)xr;
        uint32_t* dst = g_xh + (size_t)gwarp * (DIN / 2);
        for (int i = lane; i < DIN / 2; i += 32) {
            float2 v = xr2[i];
            dst[i] = h2u(__floats2half2_rn(v.x, v.y));
        }
    }

    if (lane == 0) {
        float logit[NE];
#pragma unroll
        for (int e = 0; e < NE; e++) logit[e] = acc[e] + bg[e];

        float mx = logit[0];
#pragma unroll
        for (int e = 1; e < NE; e++) mx = fmaxf(mx, logit[e]);
        float s = 0.f, ex[NE];
#pragma unroll
        for (int e = 0; e < NE; e++) { ex[e] = expf(logit[e] - mx); s += ex[e]; }
        float inv = 1.f / s;
#pragma unroll
        for (int e = 0; e < NE; e++) g_gates[gwarp * NE + e] = ex[e] * inv;

        int i0 = 0;
#pragma unroll
        for (int e = 1; e < NE; e++) if (logit[e] > logit[i0]) i0 = e;
        int i1 = -1;
#pragma unroll
        for (int e = 0; e < NE; e++)
            if (e != i0 && (i1 < 0 || logit[e] > logit[i1])) i1 = e;

        float w0 = 1.f / (1.f + expf(logit[i1] - logit[i0]));
        g_topi[gwarp * 2 + 0] = i0;
        g_topi[gwarp * 2 + 1] = i1;
        g_topw[gwarp * 2 + 0] = w0;
        g_topw[gwarp * 2 + 1] = 1.f - w0;
    }
}

// ---------------- fused W1/W2 -> fp16 convert + out zeroing ---------------------
__global__ void convert_w_zero_kernel(const float* __restrict__ W1,
                                      const float* __restrict__ W2,
                                      float* __restrict__ out) {
    size_t p = (size_t)blockIdx.x * blockDim.x + threadIdx.x;
    if (p < 2 * WQUADS) {
        const float* src;
        uint32_t* dst;
        size_t q;
        if (p < WQUADS) { q = p;          src = W1; dst = g_w1h; }
        else            { q = p - WQUADS; src = W2; dst = g_w2h; }
        float4 v = ((const float4*)src)[q];
        dst[q * 2 + 0] = h2u(__floats2half2_rn(v.x, v.y));
        dst[q * 2 + 1] = h2u(__floats2half2_rn(v.z, v.w));
    } else if (p < FUSED_ITEMS) {
        size_t q = p - 2 * WQUADS;
        ((float4*)out)[q] = make_float4(0.f, 0.f, 0.f, 0.f);
    }
}

// ---------------- fused routing + usage mean + load-balance loss ----------------
__global__ void route_usage_kernel(float* __restrict__ out, int out_size) {
    __shared__ int   hist[RT_THREADS][NE];
    __shared__ int   offs_sh[NE];
    __shared__ int   counts_sh[NE];
    __shared__ float su[RT_THREADS][NE];
    int tid = threadIdx.x;

    int h[NE];
#pragma unroll
    for (int e = 0; e < NE; e++) h[e] = 0;
    int t0 = tid * TOK_PER_TH;
    for (int i = 0; i < TOK_PER_TH; i++) {
        int t = t0 + i;
        h[g_topi[t * 2 + 0]]++;
        h[g_topi[t * 2 + 1]]++;
    }
#pragma unroll
    for (int e = 0; e < NE; e++) hist[tid][e] = h[e];
    __syncthreads();

    if (tid < NE) {
        int e = tid, s = 0;
        for (int j = 0; j < RT_THREADS; j++) {
            int v = hist[j][e];
            hist[j][e] = s;
            s += v;
        }
        counts_sh[e] = s;
        g_counts[e]  = s;
    }
    __syncthreads();

    if (tid == 0) {
        int off = 0;
        for (int e = 0; e < NE; e++) { offs_sh[e] = off; off += counts_sh[e]; }
    }
    __syncthreads();

    int base[NE];
#pragma unroll
    for (int e = 0; e < NE; e++) base[e] = offs_sh[e] + hist[tid][e];

    for (int i = 0; i < TOK_PER_TH; i++) {
        int t = t0 + i;
#pragma unroll
        for (int k = 0; k < TOPK; k++) {
            int e   = g_topi[t * 2 + k];
            int row = base[e]++;
            g_token_of_row[row] = t;
            g_wt_of_row[row]    = g_topw[t * 2 + k];
        }
    }

    // ---- usage mean + loss (deterministic fixed-order reduction) ----
    float acc[NE];
#pragma unroll
    for (int e = 0; e < NE; e++) acc[e] = 0.f;
    for (int t = tid; t < BTOK; t += RT_THREADS) {
        const float* g = g_gates + (size_t)t * NE;
#pragma unroll
        for (int e = 0; e < NE; e++) acc[e] += g[e];
    }
#pragma unroll
    for (int e = 0; e < NE; e++) su[tid][e] = acc[e];
    __syncthreads();
    if (tid == 0) {
        float loss = 0.f;
        for (int e = 0; e < NE; e++) {
            float u = 0.f;
            for (int j = 0; j < RT_THREADS; j++) u += su[j][e];
            u /= (float)BTOK;
            loss += u * u;
        }
        if (out_size > BTOK * DOUT) out[BTOK * DOUT] = (float)NE * loss;
    }
}

// ---------------- grouped GEMM: cp.async (4-stage) + fp16 HMMA (R11 config) -----
// STAGE=1: A = g_xh (gathered rows) -> g_hh (fp16x2), ReLU.
// STAGE=2: A = g_hh (contiguous)    -> atomicAdd into out (fused combine).
template <int KD, int ND, int STAGE>
__global__ void __launch_bounds__(256, 2)
moe_gemm_f16(const float* __restrict__ bias, float* __restrict__ out) {
    int t = blockIdx.x;

    int e = 0, grow0 = 0, rows = 0;
    {
        int tileacc = 0, off = 0;
        bool found = false;
#pragma unroll
        for (int ee = 0; ee < NE; ee++) {
            int c  = g_counts[ee];
            int nt = (c + BM - 1) / BM;
            if (!found && t < tileacc + nt) {
                found = true;
                e     = ee;
                int rb = (t - tileacc) * BM;
                grow0 = off + rb;
                rows  = min(BM, c - rb);
            }
            tileacc += nt;
            off     += c;
        }
        if (!found) return;
    }
    int n0 = blockIdx.y * BN;

    extern __shared__ __align__(16) uint8_t dynsmem[];
    uint32_t sbase = smem_u32(dynsmem);

    int tid = threadIdx.x, wid = tid >> 5, lane = tid & 31;
    int warp_m = wid & 3;        // 0..3 -> m offset *32
    int warp_n = wid >> 2;       // 0..1 -> n offset *64

    // ---- cp.async source pointers ----
    int arow = tid >> 1, ahalf = tid & 1;           // A: 128 rows x 2 halves
    const uint32_t* Asrc;
    if (STAGE == 1) {
        int tok = (arow < rows) ? g_token_of_row[grow0 + arow] : g_token_of_row[grow0];
        Asrc = g_xh + (size_t)tok * (KD / 2);
    } else {
        int r = min(grow0 + arow, MAXROWS - 1);
        Asrc = g_hh + (size_t)r * (KD / 2);
    }
    int bkrow = tid >> 3, bseg = tid & 7;           // B: 32 k-rows x 8 segs x2
    const uint32_t* Wsrc = (STAGE == 1 ? g_w1h : g_w2h)
                           + ((size_t)e * KD + bkrow) * (ND / 2) + n0 / 2 + bseg * 4;

    // ---- ldmatrix address bases ----
    uint32_t a_off = (uint32_t)(warp_m * 32 + (lane & 15)) * A_STRIDE
                   + (uint32_t)(lane >> 4) * 16;
    uint32_t b_off = (uint32_t)((lane & 7) + ((lane >> 3) & 1) * 8) * B_STRIDE
                   + (uint32_t)(warp_n * 64 + ((lane >> 4) & 1) * 8) * 2;

    float acc[2][8][4];
#pragma unroll
    for (int i = 0; i < 2; i++)
#pragma unroll
        for (int j = 0; j < 8; j++)
#pragma unroll
            for (int q = 0; q < 4; q++) acc[i][j][q] = 0.f;

    const int NCH = KD / BK;

    auto issue = [&](int it) {
        uint32_t base = sbase + (uint32_t)(it & (NSTAGE - 1)) * STG_BYTES;
        int k0 = it * BK;
        uint32_t dA = base + (uint32_t)arow * A_STRIDE + (uint32_t)ahalf * 32;
        const uint32_t* sa = Asrc + (k0 >> 1) + ahalf * 8;
        cp16(dA,      sa);
        cp16(dA + 16, sa + 4);
        uint32_t dB = base + A_REG + (uint32_t)bkrow * B_STRIDE + (uint32_t)bseg * 16;
        const uint32_t* sb = Wsrc + (size_t)k0 * (ND / 2);
        cp16(dB,       sb);
        cp16(dB + 128, sb + 32);
        CP_COMMIT();
    };

    // prologue: 3 chunks in flight
    issue(0);
    issue(1);
    issue(2);

    for (int it = 0; it < NCH; it++) {
        if (it < NCH - 2)       CP_WAIT2();
        else if (it == NCH - 2) CP_WAIT1();
        else                    CP_WAIT0();
        __syncthreads();
        // refill the slot consumed 2 syncs ago (race-free after the sync above)
        if (it + 3 < NCH) issue(it + 3);

        uint32_t base = sbase + (uint32_t)(it & (NSTAGE - 1)) * STG_BYTES;
        uint32_t Ab = base, Bb = base + A_REG;

#pragma unroll
        for (int h = 0; h < 2; h++) {
            uint32_t fA[2][4];
#pragma unroll
            for (int mi = 0; mi < 2; mi++) {
                uint32_t ad = a_off + (uint32_t)mi * (16 * A_STRIDE) + (uint32_t)h * 32;
                ldsm4(fA[mi], Ab + ad);
            }
#pragma unroll
            for (int n2 = 0; n2 < 4; n2++) {
                uint32_t fB[4];
                uint32_t bd = b_off + (uint32_t)h * (16 * B_STRIDE) + (uint32_t)n2 * 32;
                ldsm4t(fB, Bb + bd);
#pragma unroll
                for (int mi = 0; mi < 2; mi++) {
                    mma_f16(acc[mi][2 * n2],     fA[mi], fB[0], fB[1]);
                    mma_f16(acc[mi][2 * n2 + 1], fA[mi], fB[2], fB[3]);
                }
            }
        }
    }

    // ---- epilogue ----
#pragma unroll
    for (int mi = 0; mi < 2; mi++) {
        int m_lo = warp_m * 32 + mi * 16 + (lane >> 2);
#pragma unroll
        for (int ni = 0; ni < 8; ni++) {
            int ncol = warp_n * 64 + ni * 8 + 2 * (lane & 3);
            float b0 = bias[(size_t)e * ND + n0 + ncol];
            float b1 = bias[(size_t)e * ND + n0 + ncol + 1];
#pragma unroll
            for (int half = 0; half < 2; half++) {
                int m = m_lo + half * 8;
                if (m < rows) {
                    float v0 = acc[mi][ni][2 * half]     + b0;
                    float v1 = acc[mi][ni][2 * half + 1] + b1;
                    size_t grow = (size_t)(grow0 + m);
                    if (STAGE == 1) {
                        v0 = fmaxf(v0, 0.f);
                        v1 = fmaxf(v1, 0.f);
                        g_hh[grow * (ND / 2) + (size_t)(n0 + ncol) / 2] =
                            h2u(__floats2half2_rn(v0, v1));
                    } else {
                        // fused combine: out[token] += w * y  (2 adds/elem, IEEE-
                        // commutative onto zeroed slots -> bit-deterministic)
                        int   tok = g_token_of_row[grow];
                        float w   = g_wt_of_row[grow];
                        float* op = out + (size_t)tok * ND + n0 + ncol;
                        atomicAdd(op,     w * v0);
                        atomicAdd(op + 1, w * v1);
                    }
                }
            }
        }
    }
}

// ---------------- launch ---------------------------------------------------------

extern "C" void kernel_launch(void* const* d_in, const int* in_sizes, int n_in,
                              void* d_out, int out_size) {
    const float *x = 0, *Wg = 0, *bg = 0, *W1 = 0, *b1 = 0, *W2 = 0, *b2 = 0;
    for (int i = 0; i < n_in; i++) {
        const float* p = (const float*)d_in[i];
        switch (in_sizes[i]) {
            case BTOK * DIN:        x  = p; break;                        // 4194304
            case NE:                bg = p; break;                        // 8
            case NE * DHID:         b1 = p; break;                        // 32768
            case NE * DIN * DHID:   if (!W1) W1 = p; else W2 = p; break;  // 33554432
            case DIN * NE:          if (!Wg) Wg = p; else b2 = p; break;  // 8192
            default: break;
        }
    }
    if (!(x && Wg && bg && W1 && b1 && W2 && b2)) {
        x  = (const float*)d_in[0]; Wg = (const float*)d_in[1];
        bg = (const float*)d_in[2]; W1 = (const float*)d_in[3];
        b1 = (const float*)d_in[4]; W2 = (const float*)d_in[5];
        b2 = (const float*)d_in[6];
    }
    float* out = (float*)d_out;

    cudaFuncSetAttribute(moe_gemm_f16<DIN, DHID, 1>,
                         cudaFuncAttributeMaxDynamicSharedMemorySize, SMEM_TOTAL);
    cudaFuncSetAttribute(moe_gemm_f16<DHID, DOUT, 2>,
                         cudaFuncAttributeMaxDynamicSharedMemorySize, SMEM_TOTAL);

    gating_kernel<<<BTOK / 8, 256>>>(x, Wg, bg);                           // 1
    convert_w_zero_kernel<<<(int)((FUSED_ITEMS + 255) / 256), 256>>>(W1, W2, out); // 2
    route_usage_kernel<<<1, RT_THREADS>>>(out, out_size);                  // 3

    moe_gemm_f16<DIN, DHID, 1>                                             // 4 (ncu)
        <<<dim3(MAXTILES, DHID / BN), 256, SMEM_TOTAL>>>(b1, nullptr);

    moe_gemm_f16<DHID, DOUT, 2>                                            // 5
        <<<dim3(MAXTILES, DOUT / BN), 256, SMEM_TOTAL>>>(b2, out);
}

// round 17
// speedup vs baseline: 1.3548x; 1.0107x over previous
#include <cuda_runtime.h>
#include <cuda_fp16.h>
#include <math.h>
#include <stdint.h>

// ---------------- problem constants -------------------------------------------
#define BTOK   4096
#define DIN    1024
#define DHID   4096
#define DOUT   1024
#define NE     8
#define TOPK   2
#define MAXROWS (BTOK * TOPK)          // 8192 grouped rows, always exact
#define BM     128
#define BN     128
#define BK     32
#define MAXTILES (MAXROWS / BM + NE)   // 72 worst-case m-tiles

#define RT_THREADS 256
#define TOK_PER_TH (BTOK / RT_THREADS) // 16

// ---------------- smem tile geometry (R11-proven) --------------------------------
#define A_STRIDE 80                     // bytes per A row: 32 fp16 (64B) + 16B pad
#define B_STRIDE 272                    // bytes per B k-row: 128 fp16 (256B) + 16B pad
#define A_REG (BM * A_STRIDE)           // 10240
#define B_REG (BK * B_STRIDE)           // 8704
#define STG_BYTES (A_REG + B_REG)       // 18944 per stage
#define NSTAGE 4
#define SMEM_TOTAL (NSTAGE * STG_BYTES) // 75776 (2 CTAs/SM)

// work ranges
#define WQUADS ((size_t)NE * DIN * DHID / 4)   // 8,388,608 per W
#define ZQUADS ((size_t)BTOK * DOUT / 4)       // 1,048,576

// ---------------- device scratch (device-code-only access!) --------------------
__device__ uint32_t g_xh[BTOK * (size_t)(DIN / 2)];          // fp16x2
__device__ uint32_t g_w1h[(size_t)NE * DIN * DHID / 2];
__device__ uint32_t g_w2h[(size_t)NE * DHID * DOUT / 2];
__device__ uint32_t g_hh[MAXROWS * (size_t)(DHID / 2)];
__device__ float    g_gates[BTOK * NE];
__device__ float    g_topw[BTOK * TOPK];
__device__ int      g_topi[BTOK * TOPK];
__device__ int      g_counts[NE];
__device__ int      g_token_of_row[MAXROWS];
__device__ float    g_wt_of_row[MAXROWS];

// ---------------- helpers -------------------------------------------------------
__device__ __forceinline__ uint32_t smem_u32(const void* p) {
    uint32_t a;
    asm("{ .reg .u64 t; cvta.to.shared.u64 t, %1; cvt.u32.u64 %0, t; }"
        : "=r"(a) : "l"(p));
    return a;
}

__device__ __forceinline__ void ldsm4(uint32_t* r, uint32_t addr) {
    asm volatile("ldmatrix.sync.aligned.m8n8.x4.shared.b16 {%0,%1,%2,%3}, [%4];"
                 : "=r"(r[0]), "=r"(r[1]), "=r"(r[2]), "=r"(r[3]) : "r"(addr));
}

__device__ __forceinline__ void ldsm4t(uint32_t* r, uint32_t addr) {
    asm volatile("ldmatrix.sync.aligned.m8n8.x4.trans.shared.b16 {%0,%1,%2,%3}, [%4];"
                 : "=r"(r[0]), "=r"(r[1]), "=r"(r[2]), "=r"(r[3]) : "r"(addr));
}

__device__ __forceinline__ void mma_f16(float* c, const uint32_t* a,
                                        uint32_t b0, uint32_t b1) {
    asm volatile(
        "mma.sync.aligned.m16n8k16.row.col.f32.f16.f16.f32 "
        "{%0,%1,%2,%3}, {%4,%5,%6,%7}, {%8,%9}, {%0,%1,%2,%3};"
        : "+f"(c[0]), "+f"(c[1]), "+f"(c[2]), "+f"(c[3])
        : "r"(a[0]), "r"(a[1]), "r"(a[2]), "r"(a[3]), "r"(b0), "r"(b1));
}

__device__ __forceinline__ void cp16(uint32_t dst, const void* src) {
    asm volatile("cp.async.cg.shared.global [%0], [%1], 16;"
                 :: "r"(dst), "l"(src));
}
#define CP_COMMIT() asm volatile("cp.async.commit_group;" ::: "memory")
#define CP_WAIT2()  asm volatile("cp.async.wait_group 2;" ::: "memory")
#define CP_WAIT1()  asm volatile("cp.async.wait_group 1;" ::: "memory")
#define CP_WAIT0()  asm volatile("cp.async.wait_group 0;" ::: "memory")

__device__ __forceinline__ uint32_t h2u(__half2 h) {
    return *reinterpret_cast<uint32_t*>(&h);
}

// ---------------- fused gating + x->fp16 convert --------------------------------
__global__ void gating_kernel(const float* __restrict__ x,
                              const float* __restrict__ Wg,
                              const float* __restrict__ bg) {
    int gwarp = (blockIdx.x * blockDim.x + threadIdx.x) >> 5;
    int lane  = threadIdx.x & 31;
    if (gwarp >= BTOK) return;
    const float* xr = x + (size_t)gwarp * DIN;

    float acc[NE];
#pragma unroll
    for (int e = 0; e < NE; e++) acc[e] = 0.f;

    for (int i = lane; i < DIN; i += 32) {
        float xv = xr[i];
        const float4* wg4 = (const float4*)(Wg + (size_t)i * NE);
        float4 w0 = wg4[0];
        float4 w1 = wg4[1];
        acc[0] += xv * w0.x; acc[1] += xv * w0.y;
        acc[2] += xv * w0.z; acc[3] += xv * w0.w;
        acc[4] += xv * w1.x; acc[5] += xv * w1.y;
        acc[6] += xv * w1.z; acc[7] += xv * w1.w;
    }
#pragma unroll
    for (int e = 0; e < NE; e++)
#pragma unroll
        for (int o = 16; o > 0; o >>= 1)
            acc[e] += __shfl_xor_sync(0xffffffffu, acc[e], o);

    // convert this token's row to fp16 (all lanes; row is L1-hot)
    {
        const float2* xr2 = (const float2*)xr;
        uint32_t* dst = g_xh + (size_t)gwarp * (DIN / 2);
        for (int i = lane; i < DIN / 2; i += 32) {
            float2 v = xr2[i];
            dst[i] = h2u(__floats2half2_rn(v.x, v.y));
        }
    }

    if (lane == 0) {
        float logit[NE];
#pragma unroll
        for (int e = 0; e < NE; e++) logit[e] = acc[e] + bg[e];

        float mx = logit[0];
#pragma unroll
        for (int e = 1; e < NE; e++) mx = fmaxf(mx, logit[e]);
        float s = 0.f, ex[NE];
#pragma unroll
        for (int e = 0; e < NE; e++) { ex[e] = expf(logit[e] - mx); s += ex[e]; }
        float inv = 1.f / s;
#pragma unroll
        for (int e = 0; e < NE; e++) g_gates[gwarp * NE + e] = ex[e] * inv;

        int i0 = 0;
#pragma unroll
        for (int e = 1; e < NE; e++) if (logit[e] > logit[i0]) i0 = e;
        int i1 = -1;
#pragma unroll
        for (int e = 0; e < NE; e++)
            if (e != i0 && (i1 < 0 || logit[e] > logit[i1])) i1 = e;

        float w0 = 1.f / (1.f + expf(logit[i1] - logit[i0]));
        g_topi[gwarp * 2 + 0] = i0;
        g_topi[gwarp * 2 + 1] = i1;
        g_topw[gwarp * 2 + 0] = w0;
        g_topw[gwarp * 2 + 1] = 1.f - w0;
    }
}

// ---------------- W1 -> fp16 -----------------------------------------------------
__global__ void convert_w1_kernel(const float* __restrict__ W1) {
    size_t q = (size_t)blockIdx.x * blockDim.x + threadIdx.x;
    if (q >= WQUADS) return;
    float4 v = ((const float4*)W1)[q];
    g_w1h[q * 2 + 0] = h2u(__floats2half2_rn(v.x, v.y));
    g_w1h[q * 2 + 1] = h2u(__floats2half2_rn(v.z, v.w));
}

// ---------------- W2 -> fp16 + out zeroing --------------------------------------
__global__ void convert_w2_zero_kernel(const float* __restrict__ W2,
                                       float* __restrict__ out) {
    size_t p = (size_t)blockIdx.x * blockDim.x + threadIdx.x;
    if (p < WQUADS) {
        float4 v = ((const float4*)W2)[p];
        g_w2h[p * 2 + 0] = h2u(__floats2half2_rn(v.x, v.y));
        g_w2h[p * 2 + 1] = h2u(__floats2half2_rn(v.z, v.w));
    } else if (p < WQUADS + ZQUADS) {
        ((float4*)out)[p - WQUADS] = make_float4(0.f, 0.f, 0.f, 0.f);
    }
}

// ---------------- fused routing + usage mean + load-balance loss ----------------
__global__ void route_usage_kernel(float* __restrict__ out, int out_size) {
    __shared__ int   hist[RT_THREADS][NE];
    __shared__ int   offs_sh[NE];
    __shared__ int   counts_sh[NE];
    __shared__ float su[RT_THREADS][NE];
    int tid = threadIdx.x;

    int h[NE];
#pragma unroll
    for (int e = 0; e < NE; e++) h[e] = 0;
    int t0 = tid * TOK_PER_TH;
    for (int i = 0; i < TOK_PER_TH; i++) {
        int t = t0 + i;
        h[g_topi[t * 2 + 0]]++;
        h[g_topi[t * 2 + 1]]++;
    }
#pragma unroll
    for (int e = 0; e < NE; e++) hist[tid][e] = h[e];
    __syncthreads();

    if (tid < NE) {
        int e = tid, s = 0;
        for (int j = 0; j < RT_THREADS; j++) {
            int v = hist[j][e];
            hist[j][e] = s;
            s += v;
        }
        counts_sh[e] = s;
        g_counts[e]  = s;
    }
    __syncthreads();

    if (tid == 0) {
        int off = 0;
        for (int e = 0; e < NE; e++) { offs_sh[e] = off; off += counts_sh[e]; }
    }
    __syncthreads();

    int base[NE];
#pragma unroll
    for (int e = 0; e < NE; e++) base[e] = offs_sh[e] + hist[tid][e];

    for (int i = 0; i < TOK_PER_TH; i++) {
        int t = t0 + i;
#pragma unroll
        for (int k = 0; k < TOPK; k++) {
            int e   = g_topi[t * 2 + k];
            int row = base[e]++;
            g_token_of_row[row] = t;
            g_wt_of_row[row]    = g_topw[t * 2 + k];
        }
    }

    // ---- usage mean + loss (deterministic fixed-order reduction) ----
    float acc[NE];
#pragma unroll
    for (int e = 0; e < NE; e++) acc[e] = 0.f;
    for (int t = tid; t < BTOK; t += RT_THREADS) {
        const float* g = g_gates + (size_t)t * NE;
#pragma unroll
        for (int e = 0; e < NE; e++) acc[e] += g[e];
    }
#pragma unroll
    for (int e = 0; e < NE; e++) su[tid][e] = acc[e];
    __syncthreads();
    if (tid == 0) {
        float loss = 0.f;
        for (int e = 0; e < NE; e++) {
            float u = 0.f;
            for (int j = 0; j < RT_THREADS; j++) u += su[j][e];
            u /= (float)BTOK;
            loss += u * u;
        }
        if (out_size > BTOK * DOUT) out[BTOK * DOUT] = (float)NE * loss;
    }
}

// ---------------- grouped GEMM: cp.async (4-stage) + fp16 HMMA (R11 config) -----
// STAGE=1: A = g_xh (gathered rows) -> g_hh (fp16x2), ReLU.
// STAGE=2: A = g_hh (contiguous)    -> atomicAdd into out (fused combine).
template <int KD, int ND, int STAGE>
__global__ void __launch_bounds__(256, 2)
moe_gemm_f16(const float* __restrict__ bias, float* __restrict__ out) {
    int t = blockIdx.x;

    int e = 0, grow0 = 0, rows = 0;
    {
        int tileacc = 0, off = 0;
        bool found = false;
#pragma unroll
        for (int ee = 0; ee < NE; ee++) {
            int c  = g_counts[ee];
            int nt = (c + BM - 1) / BM;
            if (!found && t < tileacc + nt) {
                found = true;
                e     = ee;
                int rb = (t - tileacc) * BM;
                grow0 = off + rb;
                rows  = min(BM, c - rb);
            }
            tileacc += nt;
            off     += c;
        }
        if (!found) return;
    }
    int n0 = blockIdx.y * BN;

    extern __shared__ __align__(16) uint8_t dynsmem[];
    uint32_t sbase = smem_u32(dynsmem);

    int tid = threadIdx.x, wid = tid >> 5, lane = tid & 31;
    int warp_m = wid & 3;        // 0..3 -> m offset *32
    int warp_n = wid >> 2;       // 0..1 -> n offset *64

    // ---- cp.async source pointers ----
    int arow = tid >> 1, ahalf = tid & 1;           // A: 128 rows x 2 halves
    const uint32_t* Asrc;
    if (STAGE == 1) {
        int tok = (arow < rows) ? g_token_of_row[grow0 + arow] : g_token_of_row[grow0];
        Asrc = g_xh + (size_t)tok * (KD / 2);
    } else {
        int r = min(grow0 + arow, MAXROWS - 1);
        Asrc = g_hh + (size_t)r * (KD / 2);
    }
    int bkrow = tid >> 3, bseg = tid & 7;           // B: 32 k-rows x 8 segs x2
    const uint32_t* Wsrc = (STAGE == 1 ? g_w1h : g_w2h)
                           + ((size_t)e * KD + bkrow) * (ND / 2) + n0 / 2 + bseg * 4;

    // ---- ldmatrix address bases ----
    uint32_t a_off = (uint32_t)(warp_m * 32 + (lane & 15)) * A_STRIDE
                   + (uint32_t)(lane >> 4) * 16;
    uint32_t b_off = (uint32_t)((lane & 7) + ((lane >> 3) & 1) * 8) * B_STRIDE
                   + (uint32_t)(warp_n * 64 + ((lane >> 4) & 1) * 8) * 2;

    float acc[2][8][4];
#pragma unroll
    for (int i = 0; i < 2; i++)
#pragma unroll
        for (int j = 0; j < 8; j++)
#pragma unroll
            for (int q = 0; q < 4; q++) acc[i][j][q] = 0.f;

    const int NCH = KD / BK;

    auto issue = [&](int it) {
        uint32_t base = sbase + (uint32_t)(it & (NSTAGE - 1)) * STG_BYTES;
        int k0 = it * BK;
        uint32_t dA = base + (uint32_t)arow * A_STRIDE + (uint32_t)ahalf * 32;
        const uint32_t* sa = Asrc + (k0 >> 1) + ahalf * 8;
        cp16(dA,      sa);
        cp16(dA + 16, sa + 4);
        uint32_t dB = base + A_REG + (uint32_t)bkrow * B_STRIDE + (uint32_t)bseg * 16;
        const uint32_t* sb = Wsrc + (size_t)k0 * (ND / 2);
        cp16(dB,       sb);
        cp16(dB + 128, sb + 32);
        CP_COMMIT();
    };

    // prologue: 3 chunks in flight
    issue(0);
    issue(1);
    issue(2);

    for (int it = 0; it < NCH; it++) {
        if (it < NCH - 2)       CP_WAIT2();
        else if (it == NCH - 2) CP_WAIT1();
        else                    CP_WAIT0();
        __syncthreads();
        // refill the slot consumed 2 syncs ago (race-free after the sync above)
        if (it + 3 < NCH) issue(it + 3);

        uint32_t base = sbase + (uint32_t)(it & (NSTAGE - 1)) * STG_BYTES;
        uint32_t Ab = base, Bb = base + A_REG;

#pragma unroll
        for (int h = 0; h < 2; h++) {
            uint32_t fA[2][4];
#pragma unroll
            for (int mi = 0; mi < 2; mi++) {
                uint32_t ad = a_off + (uint32_t)mi * (16 * A_STRIDE) + (uint32_t)h * 32;
                ldsm4(fA[mi], Ab + ad);
            }
#pragma unroll
            for (int n2 = 0; n2 < 4; n2++) {
                uint32_t fB[4];
                uint32_t bd = b_off + (uint32_t)h * (16 * B_STRIDE) + (uint32_t)n2 * 32;
                ldsm4t(fB, Bb + bd);
#pragma unroll
                for (int mi = 0; mi < 2; mi++) {
                    mma_f16(acc[mi][2 * n2],     fA[mi], fB[0], fB[1]);
                    mma_f16(acc[mi][2 * n2 + 1], fA[mi], fB[2], fB[3]);
                }
            }
        }
    }

    // ---- epilogue ----
#pragma unroll
    for (int mi = 0; mi < 2; mi++) {
        int m_lo = warp_m * 32 + mi * 16 + (lane >> 2);
#pragma unroll
        for (int ni = 0; ni < 8; ni++) {
            int ncol = warp_n * 64 + ni * 8 + 2 * (lane & 3);
            float b0 = bias[(size_t)e * ND + n0 + ncol];
            float b1 = bias[(size_t)e * ND + n0 + ncol + 1];
#pragma unroll
            for (int half = 0; half < 2; half++) {
                int m = m_lo + half * 8;
                if (m < rows) {
                    float v0 = acc[mi][ni][2 * half]     + b0;
                    float v1 = acc[mi][ni][2 * half + 1] + b1;
                    size_t grow = (size_t)(grow0 + m);
                    if (STAGE == 1) {
                        v0 = fmaxf(v0, 0.f);
                        v1 = fmaxf(v1, 0.f);
                        g_hh[grow * (ND / 2) + (size_t)(n0 + ncol) / 2] =
                            h2u(__floats2half2_rn(v0, v1));
                    } else {
                        // fused combine: out[token] += w * y  (2 adds/elem, IEEE-
                        // commutative onto zeroed slots -> bit-deterministic)
                        int   tok = g_token_of_row[grow];
                        float w   = g_wt_of_row[grow];
                        float* op = out + (size_t)tok * ND + n0 + ncol;
                        atomicAdd(op,     w * v0);
                        atomicAdd(op + 1, w * v1);
                    }
                }
            }
        }
    }
}

// ---------------- launch ---------------------------------------------------------

extern "C" void kernel_launch(void* const* d_in, const int* in_sizes, int n_in,
                              void* d_out, int out_size) {
    const float *x = 0, *Wg = 0, *bg = 0, *W1 = 0, *b1 = 0, *W2 = 0, *b2 = 0;
    for (int i = 0; i < n_in; i++) {
        const float* p = (const float*)d_in[i];
        switch (in_sizes[i]) {
            case BTOK * DIN:        x  = p; break;                        // 4194304
            case NE:                bg = p; break;                        // 8
            case NE * DHID:         b1 = p; break;                        // 32768
            case NE * DIN * DHID:   if (!W1) W1 = p; else W2 = p; break;  // 33554432
            case DIN * NE:          if (!Wg) Wg = p; else b2 = p; break;  // 8192
            default: break;
        }
    }
    if (!(x && Wg && bg && W1 && b1 && W2 && b2)) {
        x  = (const float*)d_in[0]; Wg = (const float*)d_in[1];
        bg = (const float*)d_in[2]; W1 = (const float*)d_in[3];
        b1 = (const float*)d_in[4]; W2 = (const float*)d_in[5];
        b2 = (const float*)d_in[6];
    }
    float* out = (float*)d_out;

    // One-time setup (runs during the uncaptured correctness call).
    static bool init_done = false;
    static cudaStream_t sW = 0;
    static cudaEvent_t evFork = 0, evW1 = 0, evW2 = 0;
    static bool forked = false;
    if (!init_done) {
        init_done = true;
        forked =
            cudaStreamCreateWithFlags(&sW, cudaStreamNonBlocking) == cudaSuccess &&
            cudaEventCreateWithFlags(&evFork, cudaEventDisableTiming) == cudaSuccess &&
            cudaEventCreateWithFlags(&evW1,   cudaEventDisableTiming) == cudaSuccess &&
            cudaEventCreateWithFlags(&evW2,   cudaEventDisableTiming) == cudaSuccess;
        cudaFuncSetAttribute(moe_gemm_f16<DIN, DHID, 1>,
                             cudaFuncAttributeMaxDynamicSharedMemorySize, SMEM_TOTAL);
        cudaFuncSetAttribute(moe_gemm_f16<DHID, DOUT, 2>,
                             cudaFuncAttributeMaxDynamicSharedMemorySize, SMEM_TOTAL);
    }

    const int W1_BLKS = (int)((WQUADS + 255) / 256);
    const int W2_BLKS = (int)((WQUADS + ZQUADS + 255) / 256);

    if (forked) {
        // fork: side stream does the W converts + out zeroing
        cudaEventRecord(evFork, 0);
        cudaStreamWaitEvent(sW, evFork, 0);
        convert_w1_kernel<<<W1_BLKS, 256, 0, sW>>>(W1);
        cudaEventRecord(evW1, sW);
        convert_w2_zero_kernel<<<W2_BLKS, 256, 0, sW>>>(W2, out);
        cudaEventRecord(evW2, sW);

        // main stream: gating -> route (independent of W converts)
        gating_kernel<<<BTOK / 8, 256>>>(x, Wg, bg);
        route_usage_kernel<<<1, RT_THREADS>>>(out, out_size);

        // join: gemm1 needs W1; gemm2 needs W2 + zeroed out
        cudaStreamWaitEvent(0, evW1, 0);
        moe_gemm_f16<DIN, DHID, 1>
            <<<dim3(MAXTILES, DHID / BN), 256, SMEM_TOTAL>>>(b1, nullptr);
        cudaStreamWaitEvent(0, evW2, 0);
        moe_gemm_f16<DHID, DOUT, 2>
            <<<dim3(MAXTILES, DOUT / BN), 256, SMEM_TOTAL>>>(b2, out);
    } else {
        // serial fallback (R16 behavior)
        gating_kernel<<<BTOK / 8, 256>>>(x, Wg, bg);
        convert_w1_kernel<<<W1_BLKS, 256>>>(W1);
        convert_w2_zero_kernel<<<W2_BLKS, 256>>>(W2, out);
        route_usage_kernel<<<1, RT_THREADS>>>(out, out_size);
        moe_gemm_f16<DIN, DHID, 1>
            <<<dim3(MAXTILES, DHID / BN), 256, SMEM_TOTAL>>>(b1, nullptr);
        moe_gemm_f16<DHID, DOUT, 2>
            <<<dim3(MAXTILES, DOUT / BN), 256, SMEM_TOTAL>>>(b2, out);
    }
}